// round 6
// baseline (speedup 1.0000x reference)
#include <cuda_runtime.h>
#include <cuda_bf16.h>
#include <math.h>
#include <stdint.h>

#define B_   4
#define S_   2048
#define H_   1024
#define NH_  16
#define HD_  64
#define MTOT (B_ * S_)   // 8192

// ---------------- scratch (no allocs allowed) ----------------
__device__ float g_q[(size_t)B_ * NH_ * S_ * HD_];    // [B,NH,S,HD]
__device__ float g_k[(size_t)B_ * NH_ * S_ * HD_];
__device__ float g_v[(size_t)B_ * NH_ * S_ * HD_];
__device__ float g_ctx[(size_t)B_ * S_ * H_];         // [B,S,H]
__device__ float g_h[(size_t)B_ * S_ * H_];           // pre-LN

// ---------------- common PTX helpers ----------------
__device__ __forceinline__ void mma16816(float* c, const uint32_t* a, const uint32_t* b) {
    asm volatile(
        "mma.sync.aligned.m16n8k16.row.col.f32.bf16.bf16.f32 "
        "{%0,%1,%2,%3}, {%4,%5,%6,%7}, {%8,%9}, {%0,%1,%2,%3};\n"
        : "+f"(c[0]), "+f"(c[1]), "+f"(c[2]), "+f"(c[3])
        : "r"(a[0]), "r"(a[1]), "r"(a[2]), "r"(a[3]), "r"(b[0]), "r"(b[1]));
}
__device__ __forceinline__ void ldsm_x4(uint32_t* r, uint32_t addr) {
    asm volatile(
        "ldmatrix.sync.aligned.m8n8.x4.shared.b16 {%0,%1,%2,%3}, [%4];\n"
        : "=r"(r[0]), "=r"(r[1]), "=r"(r[2]), "=r"(r[3]) : "r"(addr));
}
__device__ __forceinline__ void ldsm_x4_t(uint32_t* r, uint32_t addr) {
    asm volatile(
        "ldmatrix.sync.aligned.m8n8.x4.trans.shared.b16 {%0,%1,%2,%3}, [%4];\n"
        : "=r"(r[0]), "=r"(r[1]), "=r"(r[2]), "=r"(r[3]) : "r"(addr));
}
// split two floats -> packed bf16x2 hi and lo
__device__ __forceinline__ void split2(float x, float y, uint32_t& hi, uint32_t& lo) {
    __nv_bfloat16 hx = __float2bfloat16(x), hy = __float2bfloat16(y);
    __nv_bfloat16 lx = __float2bfloat16(x - __bfloat162float(hx));
    __nv_bfloat16 ly = __float2bfloat16(y - __bfloat162float(hy));
    __nv_bfloat162 h2 = __halves2bfloat162(hx, hy);
    __nv_bfloat162 l2 = __halves2bfloat162(lx, ly);
    hi = *(uint32_t*)&h2;
    lo = *(uint32_t*)&l2;
}

// ============================================================
//  bf16x3 tensor-core GEMM:  C[M,N] = A[M,K] * W[N,K]^T + bias
//  gridDim.z selects weight set (QKV fused); vectorized STS.
// ============================================================
#define BM 128
#define BN 128
#define BK 32
#define LDS_PAD 8
#define LDK (BK + LDS_PAD)     // 40 halves = 80 B row stride (16B-aligned)

__global__ __launch_bounds__(256) void gemm_bf16x3(
    const float* __restrict__ A,
    const float* __restrict__ W0, const float* __restrict__ W1, const float* __restrict__ W2,
    const float* __restrict__ bias0, const float* __restrict__ bias1, const float* __restrict__ bias2,
    float* __restrict__ C0, float* __restrict__ C1, float* __restrict__ C2,
    const float* __restrict__ resid, int qkv_layout)
{
    const int K = H_, N = H_;
    const int z = blockIdx.z;
    const float* W    = (z == 0) ? W0 : (z == 1) ? W1 : W2;
    const float* bias = (z == 0) ? bias0 : (z == 1) ? bias1 : bias2;
    float*       C    = (z == 0) ? C0 : (z == 1) ? C1 : C2;

    __shared__ __nv_bfloat16 Ah[BM][LDK], Al[BM][LDK];
    __shared__ __nv_bfloat16 Bh[BN][LDK], Bl[BN][LDK];

    const int tid  = threadIdx.x;
    const int warp = tid >> 5;
    const int lane = tid & 31;
    const int rowBase = blockIdx.y * BM;
    const int colBase = blockIdx.x * BN;

    const int m0 = (warp >> 1) * 32;
    const int n0 = (warp & 1) * 64;

    const int lrow = tid >> 1;
    const int lcol = (tid & 1) * 16;
    const float* Ag = A + (size_t)(rowBase + lrow) * K + lcol;
    const float* Wg = W + (size_t)(colBase + lrow) * K + lcol;

    const int a_row = m0 + ((lane >> 3) & 1) * 8 + (lane & 7);
    const int a_col = ((lane >> 4) & 1) * 8;
    const int b_row = n0 + ((lane >> 4) & 1) * 8 + (lane & 7);
    const int b_col = ((lane >> 3) & 1) * 8;

    const uint32_t sAh = (uint32_t)__cvta_generic_to_shared(&Ah[0][0]);
    const uint32_t sAl = (uint32_t)__cvta_generic_to_shared(&Al[0][0]);
    const uint32_t sBh = (uint32_t)__cvta_generic_to_shared(&Bh[0][0]);
    const uint32_t sBl = (uint32_t)__cvta_generic_to_shared(&Bl[0][0]);

    float acc[2][8][4];
#pragma unroll
    for (int i = 0; i < 2; i++)
#pragma unroll
        for (int j = 0; j < 8; j++)
#pragma unroll
            for (int r = 0; r < 4; r++) acc[i][j][r] = 0.f;

    float4 ra[4], rb[4];
#pragma unroll
    for (int v = 0; v < 4; v++) {
        ra[v] = *(const float4*)(Ag + v * 4);
        rb[v] = *(const float4*)(Wg + v * 4);
    }

    for (int kt = 0; kt < K; kt += BK) {
        // convert + packed store (STS.128)
        {
            uint32_t ahp[8], alp[8], bhp[8], blp[8];
#pragma unroll
            for (int v = 0; v < 4; v++) {
                const float* fa = (const float*)&ra[v];
                const float* fb = (const float*)&rb[v];
                split2(fa[0], fa[1], ahp[2 * v], alp[2 * v]);
                split2(fa[2], fa[3], ahp[2 * v + 1], alp[2 * v + 1]);
                split2(fb[0], fb[1], bhp[2 * v], blp[2 * v]);
                split2(fb[2], fb[3], bhp[2 * v + 1], blp[2 * v + 1]);
            }
            float4* dAh = (float4*)&Ah[lrow][lcol];
            float4* dAl = (float4*)&Al[lrow][lcol];
            float4* dBh = (float4*)&Bh[lrow][lcol];
            float4* dBl = (float4*)&Bl[lrow][lcol];
            dAh[0] = ((float4*)ahp)[0]; dAh[1] = ((float4*)ahp)[1];
            dAl[0] = ((float4*)alp)[0]; dAl[1] = ((float4*)alp)[1];
            dBh[0] = ((float4*)bhp)[0]; dBh[1] = ((float4*)bhp)[1];
            dBl[0] = ((float4*)blp)[0]; dBl[1] = ((float4*)blp)[1];
        }
        __syncthreads();

        if (kt + BK < K) {
#pragma unroll
            for (int v = 0; v < 4; v++) {
                ra[v] = *(const float4*)(Ag + kt + BK + v * 4);
                rb[v] = *(const float4*)(Wg + kt + BK + v * 4);
            }
        }

#pragma unroll
        for (int ks = 0; ks < 2; ks++) {
            const int kb = ks * 16;
            uint32_t ah[2][4], al[2][4], bh[8][2], bl[8][2];
#pragma unroll
            for (int mi = 0; mi < 2; mi++) {
                uint32_t off = (uint32_t)(((a_row + mi * 16) * LDK) + kb + a_col) * 2;
                ldsm_x4(ah[mi], sAh + off);
                ldsm_x4(al[mi], sAl + off);
            }
#pragma unroll
            for (int p = 0; p < 4; p++) {
                uint32_t off = (uint32_t)(((b_row + p * 16) * LDK) + kb + b_col) * 2;
                uint32_t t[4];
                ldsm_x4(t, sBh + off);
                bh[2 * p][0] = t[0]; bh[2 * p][1] = t[1];
                bh[2 * p + 1][0] = t[2]; bh[2 * p + 1][1] = t[3];
                ldsm_x4(t, sBl + off);
                bl[2 * p][0] = t[0]; bl[2 * p][1] = t[1];
                bl[2 * p + 1][0] = t[2]; bl[2 * p + 1][1] = t[3];
            }
#pragma unroll
            for (int nj = 0; nj < 8; nj++)
#pragma unroll
                for (int mi = 0; mi < 2; mi++) {
                    mma16816(acc[mi][nj], ah[mi], bh[nj]);
                    mma16816(acc[mi][nj], ah[mi], bl[nj]);
                    mma16816(acc[mi][nj], al[mi], bh[nj]);
                }
        }
        __syncthreads();
    }

    const int g  = lane >> 2;
    const int t2 = (lane & 3) * 2;
#pragma unroll
    for (int mi = 0; mi < 2; mi++) {
#pragma unroll
        for (int nj = 0; nj < 8; nj++) {
            int n = colBase + n0 + nj * 8 + t2;
            float bia0 = bias[n], bia1 = bias[n + 1];
#pragma unroll
            for (int rr = 0; rr < 2; rr++) {
                int m = rowBase + m0 + mi * 16 + g + rr * 8;
                float v0 = acc[mi][nj][rr * 2 + 0] + bia0;
                float v1 = acc[mi][nj][rr * 2 + 1] + bia1;
                if (qkv_layout) {
                    int bb = m >> 11, ss = m & (S_ - 1);
                    int hh = n >> 6, dd = n & (HD_ - 1);
                    float2* dst = (float2*)&C[((((size_t)bb * NH_) + hh) * S_ + ss) * HD_ + dd];
                    *dst = make_float2(v0, v1);
                } else {
                    const float2 rs = *(const float2*)&resid[(size_t)m * N + n];
                    *(float2*)&C[(size_t)m * N + n] = make_float2(v0 + rs.x, v1 + rs.y);
                }
            }
        }
    }
}

// ============================================================
//  MMA flash attention (bf16x3 emulated), 64 q x 64 kv tiles
//  128 threads: warp w owns q rows [16w, 16w+16)
// ============================================================
#define FLDV 72   // padded row stride (halves) = 144 B (16B-aligned)

__global__ __launch_bounds__(128) void flash_mma(
    const float* __restrict__ Q, const float* __restrict__ Kg,
    const float* __restrict__ Vg, float* __restrict__ ctx)
{
    __shared__ __nv_bfloat16 Kh[64][FLDV], Kl[64][FLDV];
    __shared__ __nv_bfloat16 Vh[64][FLDV], Vl[64][FLDV];

    const int b = blockIdx.z;
    const int h = blockIdx.y;
    const int tid  = threadIdx.x;
    const int warp = tid >> 5;
    const int lane = tid & 31;
    const int q0 = blockIdx.x * 64;

    const size_t headBase = (((size_t)b * NH_ + h) * S_) * HD_;
    const float* qbase = Q  + headBase;
    const float* kbase = Kg + headBase;
    const float* vbase = Vg + headBase;

    const int lrow = tid >> 1;
    const int lcol = (tid & 1) * 32;

    const int a_row = ((lane >> 3) & 1) * 8 + (lane & 7);
    const int a_col = ((lane >> 4) & 1) * 8;
    const int b_row = ((lane >> 4) & 1) * 8 + (lane & 7);
    const int b_col = ((lane >> 3) & 1) * 8;
    const int v_row = ((lane >> 3) & 1) * 8 + (lane & 7);
    const int v_col = ((lane >> 4) & 1) * 8;

    const uint32_t sKh = (uint32_t)__cvta_generic_to_shared(&Kh[0][0]);
    const uint32_t sKl = (uint32_t)__cvta_generic_to_shared(&Kl[0][0]);
    const uint32_t sVh = (uint32_t)__cvta_generic_to_shared(&Vh[0][0]);
    const uint32_t sVl = (uint32_t)__cvta_generic_to_shared(&Vl[0][0]);

    // ---- stage Q (scaled by 1/8) through K smem, packed stores ----
    {
        const float* qg = qbase + (size_t)(q0 + lrow) * HD_ + lcol;
        uint32_t qhp[16], qlp[16];
#pragma unroll
        for (int v = 0; v < 8; v++) {
            float4 f = *(const float4*)(qg + v * 4);
            split2(f.x * 0.125f, f.y * 0.125f, qhp[2 * v], qlp[2 * v]);
            split2(f.z * 0.125f, f.w * 0.125f, qhp[2 * v + 1], qlp[2 * v + 1]);
        }
        float4* dH = (float4*)&Kh[lrow][lcol];
        float4* dL = (float4*)&Kl[lrow][lcol];
#pragma unroll
        for (int i = 0; i < 4; i++) {
            dH[i] = ((float4*)qhp)[i];
            dL[i] = ((float4*)qlp)[i];
        }
    }
    __syncthreads();

    uint32_t qh[4][4], ql[4][4];
#pragma unroll
    for (int ks = 0; ks < 4; ks++) {
        uint32_t off = (uint32_t)(((warp * 16 + a_row) * FLDV) + ks * 16 + a_col) * 2;
        ldsm_x4(qh[ks], sKh + off);
        ldsm_x4(ql[ks], sKl + off);
    }
    __syncthreads();

    float o[8][4];
#pragma unroll
    for (int dn = 0; dn < 8; dn++)
#pragma unroll
        for (int e = 0; e < 4; e++) o[dn][e] = 0.f;
    float mrun[2] = {-1e30f, -1e30f};
    float lrun[2] = {0.f, 0.f};

    for (int j0 = 0; j0 < S_; j0 += 64) {
        // ---- load + convert K,V tiles (packed STS.128) ----
        {
            const float* kg = kbase + (size_t)(j0 + lrow) * HD_ + lcol;
            const float* vg = vbase + (size_t)(j0 + lrow) * HD_ + lcol;
            uint32_t khp[16], klp[16], vhp[16], vlp[16];
#pragma unroll
            for (int v = 0; v < 8; v++) {
                float4 fk = *(const float4*)(kg + v * 4);
                float4 fv = *(const float4*)(vg + v * 4);
                split2(fk.x, fk.y, khp[2 * v], klp[2 * v]);
                split2(fk.z, fk.w, khp[2 * v + 1], klp[2 * v + 1]);
                split2(fv.x, fv.y, vhp[2 * v], vlp[2 * v]);
                split2(fv.z, fv.w, vhp[2 * v + 1], vlp[2 * v + 1]);
            }
            float4* dKh = (float4*)&Kh[lrow][lcol];
            float4* dKl = (float4*)&Kl[lrow][lcol];
            float4* dVh = (float4*)&Vh[lrow][lcol];
            float4* dVl = (float4*)&Vl[lrow][lcol];
#pragma unroll
            for (int i = 0; i < 4; i++) {
                dKh[i] = ((float4*)khp)[i];
                dKl[i] = ((float4*)klp)[i];
                dVh[i] = ((float4*)vhp)[i];
                dVl[i] = ((float4*)vlp)[i];
            }
        }
        __syncthreads();

        // ---- S = Q K^T ----
        float sacc[8][4];
#pragma unroll
        for (int nj = 0; nj < 8; nj++)
#pragma unroll
            for (int e = 0; e < 4; e++) sacc[nj][e] = 0.f;

#pragma unroll
        for (int ks = 0; ks < 4; ks++) {
            uint32_t bh[8][2], bl[8][2];
#pragma unroll
            for (int p = 0; p < 4; p++) {
                uint32_t off = (uint32_t)(((p * 16 + b_row) * FLDV) + ks * 16 + b_col) * 2;
                uint32_t t[4];
                ldsm_x4(t, sKh + off);
                bh[2 * p][0] = t[0]; bh[2 * p][1] = t[1];
                bh[2 * p + 1][0] = t[2]; bh[2 * p + 1][1] = t[3];
                ldsm_x4(t, sKl + off);
                bl[2 * p][0] = t[0]; bl[2 * p][1] = t[1];
                bl[2 * p + 1][0] = t[2]; bl[2 * p + 1][1] = t[3];
            }
#pragma unroll
            for (int nj = 0; nj < 8; nj++) {
                mma16816(sacc[nj], qh[ks], bh[nj]);
                mma16816(sacc[nj], ql[ks], bh[nj]);
                mma16816(sacc[nj], qh[ks], bl[nj]);
            }
        }

        // ---- online softmax ----
        float mloc[2] = {-1e30f, -1e30f};
#pragma unroll
        for (int nj = 0; nj < 8; nj++) {
            mloc[0] = fmaxf(mloc[0], fmaxf(sacc[nj][0], sacc[nj][1]));
            mloc[1] = fmaxf(mloc[1], fmaxf(sacc[nj][2], sacc[nj][3]));
        }
#pragma unroll
        for (int r = 0; r < 2; r++) {
            mloc[r] = fmaxf(mloc[r], __shfl_xor_sync(0xFFFFFFFFu, mloc[r], 1));
            mloc[r] = fmaxf(mloc[r], __shfl_xor_sync(0xFFFFFFFFu, mloc[r], 2));
        }
        float corr[2];
#pragma unroll
        for (int r = 0; r < 2; r++) {
            float mnew = fmaxf(mrun[r], mloc[r]);
            corr[r] = __expf(mrun[r] - mnew);
            mrun[r] = mnew;
        }
        float psum[2] = {0.f, 0.f};
#pragma unroll
        for (int nj = 0; nj < 8; nj++) {
            float p0 = __expf(sacc[nj][0] - mrun[0]);
            float p1 = __expf(sacc[nj][1] - mrun[0]);
            float p2 = __expf(sacc[nj][2] - mrun[1]);
            float p3 = __expf(sacc[nj][3] - mrun[1]);
            sacc[nj][0] = p0; sacc[nj][1] = p1;
            sacc[nj][2] = p2; sacc[nj][3] = p3;
            psum[0] += p0 + p1;
            psum[1] += p2 + p3;
        }
#pragma unroll
        for (int r = 0; r < 2; r++) {
            psum[r] += __shfl_xor_sync(0xFFFFFFFFu, psum[r], 1);
            psum[r] += __shfl_xor_sync(0xFFFFFFFFu, psum[r], 2);
            lrun[r] = lrun[r] * corr[r] + psum[r];
        }
#pragma unroll
        for (int dn = 0; dn < 8; dn++) {
            o[dn][0] *= corr[0]; o[dn][1] *= corr[0];
            o[dn][2] *= corr[1]; o[dn][3] *= corr[1];
        }

        // ---- repack P -> A-frags ----
        uint32_t ph[4][4], pl[4][4];
#pragma unroll
        for (int ks = 0; ks < 4; ks++) {
            const float* c0 = sacc[2 * ks];
            const float* c1 = sacc[2 * ks + 1];
            split2(c0[0], c0[1], ph[ks][0], pl[ks][0]);
            split2(c0[2], c0[3], ph[ks][1], pl[ks][1]);
            split2(c1[0], c1[1], ph[ks][2], pl[ks][2]);
            split2(c1[2], c1[3], ph[ks][3], pl[ks][3]);
        }

        // ---- O += P V ----
#pragma unroll
        for (int ks = 0; ks < 4; ks++) {
            uint32_t vbh[8][2], vbl[8][2];
#pragma unroll
            for (int p = 0; p < 4; p++) {
                uint32_t off = (uint32_t)(((ks * 16 + v_row) * FLDV) + p * 16 + v_col) * 2;
                uint32_t t[4];
                ldsm_x4_t(t, sVh + off);
                vbh[2 * p][0] = t[0]; vbh[2 * p][1] = t[1];
                vbh[2 * p + 1][0] = t[2]; vbh[2 * p + 1][1] = t[3];
                ldsm_x4_t(t, sVl + off);
                vbl[2 * p][0] = t[0]; vbl[2 * p][1] = t[1];
                vbl[2 * p + 1][0] = t[2]; vbl[2 * p + 1][1] = t[3];
            }
#pragma unroll
            for (int dn = 0; dn < 8; dn++) {
                mma16816(o[dn], ph[ks], vbh[dn]);
                mma16816(o[dn], pl[ks], vbh[dn]);
                mma16816(o[dn], ph[ks], vbl[dn]);
            }
        }
        __syncthreads();
    }

    // ---- finalize + write ctx [B,S,H] ----
    const int g  = lane >> 2;
    const int t2 = (lane & 3) * 2;
    float inv0 = 1.0f / lrun[0];
    float inv1 = 1.0f / lrun[1];
#pragma unroll
    for (int dn = 0; dn < 8; dn++) {
        int d = h * HD_ + dn * 8 + t2;
        int m0g = q0 + warp * 16 + g;
        float* dst0 = &ctx[((size_t)b * S_ + m0g) * H_ + d];
        float* dst1 = &ctx[((size_t)b * S_ + m0g + 8) * H_ + d];
        *(float2*)dst0 = make_float2(o[dn][0] * inv0, o[dn][1] * inv0);
        *(float2*)dst1 = make_float2(o[dn][2] * inv1, o[dn][3] * inv1);
    }
}

// ---------------- layernorm (one block per row) --------------------------
__global__ __launch_bounds__(256) void layernorm_k(
    const float* __restrict__ hin, const float* __restrict__ gamma,
    const float* __restrict__ beta, float* __restrict__ out)
{
    const int row = blockIdx.x;
    const int t = threadIdx.x;
    const float* hp = hin + (size_t)row * H_;
    float* op = out + (size_t)row * H_;

    float4 x4 = ((const float4*)hp)[t];
    float sum = x4.x + x4.y + x4.z + x4.w;
    float sq  = x4.x * x4.x + x4.y * x4.y + x4.z * x4.z + x4.w * x4.w;

#pragma unroll
    for (int off = 16; off > 0; off >>= 1) {
        sum += __shfl_xor_sync(0xFFFFFFFFu, sum, off);
        sq  += __shfl_xor_sync(0xFFFFFFFFu, sq,  off);
    }
    __shared__ float ssum[8], ssq[8];
    const int wid = t >> 5, lid = t & 31;
    if (lid == 0) { ssum[wid] = sum; ssq[wid] = sq; }
    __syncthreads();
    if (wid == 0) {
        float a = (lid < 8) ? ssum[lid] : 0.f;
        float b = (lid < 8) ? ssq[lid]  : 0.f;
#pragma unroll
        for (int off = 4; off > 0; off >>= 1) {
            a += __shfl_xor_sync(0xFFFFFFFFu, a, off);
            b += __shfl_xor_sync(0xFFFFFFFFu, b, off);
        }
        if (lid == 0) { ssum[0] = a; ssq[0] = b; }
    }
    __syncthreads();
    const float mean = ssum[0] * (1.0f / H_);
    const float var  = ssq[0] * (1.0f / H_) - mean * mean;
    const float rstd = rsqrtf(var + 1e-12f);

    float4 g4 = ((const float4*)gamma)[t];
    float4 b4 = ((const float4*)beta)[t];
    float4 o4;
    o4.x = g4.x * (x4.x - mean) * rstd + b4.x;
    o4.y = g4.y * (x4.y - mean) * rstd + b4.y;
    o4.z = g4.z * (x4.z - mean) * rstd + b4.z;
    o4.w = g4.w * (x4.w - mean) * rstd + b4.w;
    ((float4*)op)[t] = o4;
}

// ---------------- launch ----------------
extern "C" void kernel_launch(void* const* d_in, const int* in_sizes, int n_in,
                              void* d_out, int out_size)
{
    const float* x     = (const float*)d_in[0];
    const float* wq    = (const float*)d_in[1];
    const float* bq    = (const float*)d_in[2];
    const float* wk    = (const float*)d_in[3];
    const float* bk    = (const float*)d_in[4];
    const float* wv    = (const float*)d_in[5];
    const float* bv    = (const float*)d_in[6];
    const float* wo    = (const float*)d_in[7];
    const float* bo    = (const float*)d_in[8];
    const float* gamma = (const float*)d_in[9];
    const float* beta  = (const float*)d_in[10];

    float *q, *k, *v, *ctx, *hbuf;
    cudaGetSymbolAddress((void**)&q,    g_q);
    cudaGetSymbolAddress((void**)&k,    g_k);
    cudaGetSymbolAddress((void**)&v,    g_v);
    cudaGetSymbolAddress((void**)&ctx,  g_ctx);
    cudaGetSymbolAddress((void**)&hbuf, g_h);

    dim3 tb(256);

    // fused QKV projections (gridDim.z picks the weight set)
    gemm_bf16x3<<<dim3(H_ / BN, MTOT / BM, 3), tb>>>(
        x, wq, wk, wv, bq, bk, bv, q, k, v, nullptr, 1);

    flash_mma<<<dim3(S_ / 64, NH_, B_), 128>>>(q, k, v, ctx);

    // output projection + residual
    gemm_bf16x3<<<dim3(H_ / BN, MTOT / BM, 1), tb>>>(
        ctx, wo, wo, wo, bo, bo, bo, hbuf, hbuf, hbuf, x, 0);

    layernorm_k<<<MTOT, 256>>>(hbuf, gamma, beta, (float*)d_out);
}

// round 8
// speedup vs baseline: 1.1559x; 1.1559x over previous
#include <cuda_runtime.h>
#include <cuda_bf16.h>
#include <math.h>
#include <stdint.h>

#define B_   4
#define S_   2048
#define H_   1024
#define NH_  16
#define HD_  64
#define MTOT (B_ * S_)   // 8192

// ---------------- scratch (no allocs allowed) ----------------
__device__ float g_q[(size_t)B_ * NH_ * S_ * HD_];    // [B,NH,S,HD]
__device__ float g_k[(size_t)B_ * NH_ * S_ * HD_];
__device__ float g_v[(size_t)B_ * NH_ * S_ * HD_];
__device__ float g_ctx[(size_t)B_ * S_ * H_];         // [B,S,H]
__device__ float g_h[(size_t)B_ * S_ * H_];           // pre-LN

// ---------------- common PTX helpers ----------------
__device__ __forceinline__ void mma16816(float* c, const uint32_t* a, const uint32_t* b) {
    asm volatile(
        "mma.sync.aligned.m16n8k16.row.col.f32.bf16.bf16.f32 "
        "{%0,%1,%2,%3}, {%4,%5,%6,%7}, {%8,%9}, {%0,%1,%2,%3};\n"
        : "+f"(c[0]), "+f"(c[1]), "+f"(c[2]), "+f"(c[3])
        : "r"(a[0]), "r"(a[1]), "r"(a[2]), "r"(a[3]), "r"(b[0]), "r"(b[1]));
}
__device__ __forceinline__ void ldsm_x4(uint32_t* r, uint32_t addr) {
    asm volatile(
        "ldmatrix.sync.aligned.m8n8.x4.shared.b16 {%0,%1,%2,%3}, [%4];\n"
        : "=r"(r[0]), "=r"(r[1]), "=r"(r[2]), "=r"(r[3]) : "r"(addr));
}
__device__ __forceinline__ void ldsm_x4_t(uint32_t* r, uint32_t addr) {
    asm volatile(
        "ldmatrix.sync.aligned.m8n8.x4.trans.shared.b16 {%0,%1,%2,%3}, [%4];\n"
        : "=r"(r[0]), "=r"(r[1]), "=r"(r[2]), "=r"(r[3]) : "r"(addr));
}
// split two floats -> packed bf16x2 hi and lo
__device__ __forceinline__ void split2(float x, float y, uint32_t& hi, uint32_t& lo) {
    __nv_bfloat16 hx = __float2bfloat16(x), hy = __float2bfloat16(y);
    __nv_bfloat16 lx = __float2bfloat16(x - __bfloat162float(hx));
    __nv_bfloat16 ly = __float2bfloat16(y - __bfloat162float(hy));
    __nv_bfloat162 h2 = __halves2bfloat162(hx, hy);
    __nv_bfloat162 l2 = __halves2bfloat162(lx, ly);
    hi = *(uint32_t*)&h2;
    lo = *(uint32_t*)&l2;
}

// ============================================================
//  bf16x3 tensor-core GEMM:  C[M,N] = A[M,K] * W[N,K]^T + bias
//  gridDim.z selects weight set (QKV fused); vectorized STS.
// ============================================================
#define BM 128
#define BN 128
#define BK 32
#define LDS_PAD 8
#define LDK (BK + LDS_PAD)     // 40 halves = 80 B row stride (16B-aligned)

__global__ __launch_bounds__(256) void gemm_bf16x3(
    const float* __restrict__ A,
    const float* __restrict__ W0, const float* __restrict__ W1, const float* __restrict__ W2,
    const float* __restrict__ bias0, const float* __restrict__ bias1, const float* __restrict__ bias2,
    float* __restrict__ C0, float* __restrict__ C1, float* __restrict__ C2,
    const float* __restrict__ resid, int qkv_layout)
{
    const int K = H_, N = H_;
    const int z = blockIdx.z;
    const float* W    = (z == 0) ? W0 : (z == 1) ? W1 : W2;
    const float* bias = (z == 0) ? bias0 : (z == 1) ? bias1 : bias2;
    float*       C    = (z == 0) ? C0 : (z == 1) ? C1 : C2;

    __shared__ __nv_bfloat16 Ah[BM][LDK], Al[BM][LDK];
    __shared__ __nv_bfloat16 Bh[BN][LDK], Bl[BN][LDK];

    const int tid  = threadIdx.x;
    const int warp = tid >> 5;
    const int lane = tid & 31;
    const int rowBase = blockIdx.y * BM;
    const int colBase = blockIdx.x * BN;

    const int m0 = (warp >> 1) * 32;
    const int n0 = (warp & 1) * 64;

    const int lrow = tid >> 1;
    const int lcol = (tid & 1) * 16;
    const float* Ag = A + (size_t)(rowBase + lrow) * K + lcol;
    const float* Wg = W + (size_t)(colBase + lrow) * K + lcol;

    const int a_row = m0 + ((lane >> 3) & 1) * 8 + (lane & 7);
    const int a_col = ((lane >> 4) & 1) * 8;
    const int b_row = n0 + ((lane >> 4) & 1) * 8 + (lane & 7);
    const int b_col = ((lane >> 3) & 1) * 8;

    const uint32_t sAh = (uint32_t)__cvta_generic_to_shared(&Ah[0][0]);
    const uint32_t sAl = (uint32_t)__cvta_generic_to_shared(&Al[0][0]);
    const uint32_t sBh = (uint32_t)__cvta_generic_to_shared(&Bh[0][0]);
    const uint32_t sBl = (uint32_t)__cvta_generic_to_shared(&Bl[0][0]);

    float acc[2][8][4];
#pragma unroll
    for (int i = 0; i < 2; i++)
#pragma unroll
        for (int j = 0; j < 8; j++)
#pragma unroll
            for (int r = 0; r < 4; r++) acc[i][j][r] = 0.f;

    float4 ra[4], rb[4];
#pragma unroll
    for (int v = 0; v < 4; v++) {
        ra[v] = *(const float4*)(Ag + v * 4);
        rb[v] = *(const float4*)(Wg + v * 4);
    }

    for (int kt = 0; kt < K; kt += BK) {
        // convert + packed store (STS.128)
        {
            uint32_t ahp[8], alp[8], bhp[8], blp[8];
#pragma unroll
            for (int v = 0; v < 4; v++) {
                const float* fa = (const float*)&ra[v];
                const float* fb = (const float*)&rb[v];
                split2(fa[0], fa[1], ahp[2 * v], alp[2 * v]);
                split2(fa[2], fa[3], ahp[2 * v + 1], alp[2 * v + 1]);
                split2(fb[0], fb[1], bhp[2 * v], blp[2 * v]);
                split2(fb[2], fb[3], bhp[2 * v + 1], blp[2 * v + 1]);
            }
            float4* dAh = (float4*)&Ah[lrow][lcol];
            float4* dAl = (float4*)&Al[lrow][lcol];
            float4* dBh = (float4*)&Bh[lrow][lcol];
            float4* dBl = (float4*)&Bl[lrow][lcol];
            dAh[0] = ((float4*)ahp)[0]; dAh[1] = ((float4*)ahp)[1];
            dAl[0] = ((float4*)alp)[0]; dAl[1] = ((float4*)alp)[1];
            dBh[0] = ((float4*)bhp)[0]; dBh[1] = ((float4*)bhp)[1];
            dBl[0] = ((float4*)blp)[0]; dBl[1] = ((float4*)blp)[1];
        }
        __syncthreads();

        if (kt + BK < K) {
#pragma unroll
            for (int v = 0; v < 4; v++) {
                ra[v] = *(const float4*)(Ag + kt + BK + v * 4);
                rb[v] = *(const float4*)(Wg + kt + BK + v * 4);
            }
        }

#pragma unroll
        for (int ks = 0; ks < 2; ks++) {
            const int kb = ks * 16;
            uint32_t ah[2][4], al[2][4], bh[8][2], bl[8][2];
#pragma unroll
            for (int mi = 0; mi < 2; mi++) {
                uint32_t off = (uint32_t)(((a_row + mi * 16) * LDK) + kb + a_col) * 2;
                ldsm_x4(ah[mi], sAh + off);
                ldsm_x4(al[mi], sAl + off);
            }
#pragma unroll
            for (int p = 0; p < 4; p++) {
                uint32_t off = (uint32_t)(((b_row + p * 16) * LDK) + kb + b_col) * 2;
                uint32_t t[4];
                ldsm_x4(t, sBh + off);
                bh[2 * p][0] = t[0]; bh[2 * p][1] = t[1];
                bh[2 * p + 1][0] = t[2]; bh[2 * p + 1][1] = t[3];
                ldsm_x4(t, sBl + off);
                bl[2 * p][0] = t[0]; bl[2 * p][1] = t[1];
                bl[2 * p + 1][0] = t[2]; bl[2 * p + 1][1] = t[3];
            }
#pragma unroll
            for (int nj = 0; nj < 8; nj++)
#pragma unroll
                for (int mi = 0; mi < 2; mi++) {
                    mma16816(acc[mi][nj], ah[mi], bh[nj]);
                    mma16816(acc[mi][nj], ah[mi], bl[nj]);
                    mma16816(acc[mi][nj], al[mi], bh[nj]);
                }
        }
        __syncthreads();
    }

    const int g  = lane >> 2;
    const int t2 = (lane & 3) * 2;
#pragma unroll
    for (int mi = 0; mi < 2; mi++) {
#pragma unroll
        for (int nj = 0; nj < 8; nj++) {
            int n = colBase + n0 + nj * 8 + t2;
            float bia0 = bias[n], bia1 = bias[n + 1];
#pragma unroll
            for (int rr = 0; rr < 2; rr++) {
                int m = rowBase + m0 + mi * 16 + g + rr * 8;
                float v0 = acc[mi][nj][rr * 2 + 0] + bia0;
                float v1 = acc[mi][nj][rr * 2 + 1] + bia1;
                if (qkv_layout) {
                    int bb = m >> 11, ss = m & (S_ - 1);
                    int hh = n >> 6, dd = n & (HD_ - 1);
                    float2* dst = (float2*)&C[((((size_t)bb * NH_) + hh) * S_ + ss) * HD_ + dd];
                    *dst = make_float2(v0, v1);
                } else {
                    const float2 rs = *(const float2*)&resid[(size_t)m * N + n];
                    *(float2*)&C[(size_t)m * N + n] = make_float2(v0 + rs.x, v1 + rs.y);
                }
            }
        }
    }
}

// ============================================================
//  MMA flash attention (bf16x3), 128 q x 64 kv tiles,
//  256 threads (8 warps x 16 q rows), K/V register prefetch.
// ============================================================
#define FLDV 72   // padded row stride (halves) = 144 B; conflict-free STS.128 + ldsm

__global__ __launch_bounds__(256) void flash_mma(
    const float* __restrict__ Q, const float* __restrict__ Kg,
    const float* __restrict__ Vg, float* __restrict__ ctx)
{
    __shared__ __nv_bfloat16 Kh[64][FLDV], Kl[64][FLDV];
    __shared__ __nv_bfloat16 Vh[64][FLDV], Vl[64][FLDV];

    const int b = blockIdx.z;
    const int h = blockIdx.y;
    const int tid  = threadIdx.x;
    const int warp = tid >> 5;
    const int lane = tid & 31;
    const int q0 = blockIdx.x * 128;

    const size_t headBase = (((size_t)b * NH_ + h) * S_) * HD_;
    const float* qbase = Q  + headBase;
    const float* kbase = Kg + headBase;
    const float* vbase = Vg + headBase;

    // cooperative K/V load mapping: thread t -> row t>>2, cols (t&3)*16..+15
    const int lrow = tid >> 2;
    const int lcol = (tid & 3) * 16;

    // ldmatrix lane patterns (B operand / V-trans), same as proven R4 code
    const int b_row = ((lane >> 4) & 1) * 8 + (lane & 7);
    const int b_col = ((lane >> 3) & 1) * 8;
    const int v_row = ((lane >> 3) & 1) * 8 + (lane & 7);
    const int v_col = ((lane >> 4) & 1) * 8;

    const uint32_t sKh = (uint32_t)__cvta_generic_to_shared(&Kh[0][0]);
    const uint32_t sKl = (uint32_t)__cvta_generic_to_shared(&Kl[0][0]);
    const uint32_t sVh = (uint32_t)__cvta_generic_to_shared(&Vh[0][0]);
    const uint32_t sVl = (uint32_t)__cvta_generic_to_shared(&Vl[0][0]);

    const int g  = lane >> 2;        // C/A-frag row group
    const int t2 = (lane & 3) * 2;   // C/A-frag col pair

    // ---- Q directly from gmem into A-fragments (scale folded) ----
    uint32_t qh[4][4], ql[4][4];
    {
        const float* qr0 = qbase + (size_t)(q0 + warp * 16 + g) * HD_;
        const float* qr1 = qr0 + 8 * HD_;
#pragma unroll
        for (int ks = 0; ks < 4; ks++) {
            int c = ks * 16 + t2;
            float2 f00 = *(const float2*)(qr0 + c);
            float2 f10 = *(const float2*)(qr1 + c);
            float2 f01 = *(const float2*)(qr0 + c + 8);
            float2 f11 = *(const float2*)(qr1 + c + 8);
            split2(f00.x * 0.125f, f00.y * 0.125f, qh[ks][0], ql[ks][0]);
            split2(f10.x * 0.125f, f10.y * 0.125f, qh[ks][1], ql[ks][1]);
            split2(f01.x * 0.125f, f01.y * 0.125f, qh[ks][2], ql[ks][2]);
            split2(f11.x * 0.125f, f11.y * 0.125f, qh[ks][3], ql[ks][3]);
        }
    }

    float o[8][4];
#pragma unroll
    for (int dn = 0; dn < 8; dn++)
#pragma unroll
        for (int e = 0; e < 4; e++) o[dn][e] = 0.f;
    float mrun[2] = {-1e30f, -1e30f};
    float lrun[2] = {0.f, 0.f};

    // ---- prefetch tile 0 into registers ----
    float4 kf[4], vf[4];
    {
        const float* kg = kbase + (size_t)lrow * HD_ + lcol;
        const float* vg = vbase + (size_t)lrow * HD_ + lcol;
#pragma unroll
        for (int i = 0; i < 4; i++) {
            kf[i] = *(const float4*)(kg + i * 4);
            vf[i] = *(const float4*)(vg + i * 4);
        }
    }

    for (int j0 = 0; j0 < S_; j0 += 64) {
        // ---- split + packed store of current tile ----
        {
            uint32_t khp[8], klp[8], vhp[8], vlp[8];
#pragma unroll
            for (int i = 0; i < 4; i++) {
                split2(kf[i].x, kf[i].y, khp[2 * i], klp[2 * i]);
                split2(kf[i].z, kf[i].w, khp[2 * i + 1], klp[2 * i + 1]);
                split2(vf[i].x, vf[i].y, vhp[2 * i], vlp[2 * i]);
                split2(vf[i].z, vf[i].w, vhp[2 * i + 1], vlp[2 * i + 1]);
            }
            float4* dKh = (float4*)&Kh[lrow][lcol];
            float4* dKl = (float4*)&Kl[lrow][lcol];
            float4* dVh = (float4*)&Vh[lrow][lcol];
            float4* dVl = (float4*)&Vl[lrow][lcol];
            dKh[0] = ((float4*)khp)[0]; dKh[1] = ((float4*)khp)[1];
            dKl[0] = ((float4*)klp)[0]; dKl[1] = ((float4*)klp)[1];
            dVh[0] = ((float4*)vhp)[0]; dVh[1] = ((float4*)vhp)[1];
            dVl[0] = ((float4*)vlp)[0]; dVl[1] = ((float4*)vlp)[1];
        }
        __syncthreads();

        // ---- prefetch next tile (LDGs fly during MMA) ----
        if (j0 + 64 < S_) {
            const float* kg = kbase + (size_t)(j0 + 64 + lrow) * HD_ + lcol;
            const float* vg = vbase + (size_t)(j0 + 64 + lrow) * HD_ + lcol;
#pragma unroll
            for (int i = 0; i < 4; i++) {
                kf[i] = *(const float4*)(kg + i * 4);
                vf[i] = *(const float4*)(vg + i * 4);
            }
        }

        // ---- S = Q K^T ----
        float sacc[8][4];
#pragma unroll
        for (int nj = 0; nj < 8; nj++)
#pragma unroll
            for (int e = 0; e < 4; e++) sacc[nj][e] = 0.f;

#pragma unroll
        for (int ks = 0; ks < 4; ks++) {
            uint32_t bh[8][2], bl[8][2];
#pragma unroll
            for (int p = 0; p < 4; p++) {
                uint32_t off = (uint32_t)(((p * 16 + b_row) * FLDV) + ks * 16 + b_col) * 2;
                uint32_t t[4];
                ldsm_x4(t, sKh + off);
                bh[2 * p][0] = t[0]; bh[2 * p][1] = t[1];
                bh[2 * p + 1][0] = t[2]; bh[2 * p + 1][1] = t[3];
                ldsm_x4(t, sKl + off);
                bl[2 * p][0] = t[0]; bl[2 * p][1] = t[1];
                bl[2 * p + 1][0] = t[2]; bl[2 * p + 1][1] = t[3];
            }
#pragma unroll
            for (int nj = 0; nj < 8; nj++) {
                mma16816(sacc[nj], qh[ks], bh[nj]);
                mma16816(sacc[nj], ql[ks], bh[nj]);
                mma16816(sacc[nj], qh[ks], bl[nj]);
            }
        }

        // ---- online softmax (rows g and g+8 per thread) ----
        float mloc[2] = {-1e30f, -1e30f};
#pragma unroll
        for (int nj = 0; nj < 8; nj++) {
            mloc[0] = fmaxf(mloc[0], fmaxf(sacc[nj][0], sacc[nj][1]));
            mloc[1] = fmaxf(mloc[1], fmaxf(sacc[nj][2], sacc[nj][3]));
        }
#pragma unroll
        for (int r = 0; r < 2; r++) {
            mloc[r] = fmaxf(mloc[r], __shfl_xor_sync(0xFFFFFFFFu, mloc[r], 1));
            mloc[r] = fmaxf(mloc[r], __shfl_xor_sync(0xFFFFFFFFu, mloc[r], 2));
        }
        float corr[2];
#pragma unroll
        for (int r = 0; r < 2; r++) {
            float mnew = fmaxf(mrun[r], mloc[r]);
            corr[r] = __expf(mrun[r] - mnew);
            mrun[r] = mnew;
        }
        float psum[2] = {0.f, 0.f};
#pragma unroll
        for (int nj = 0; nj < 8; nj++) {
            float p0 = __expf(sacc[nj][0] - mrun[0]);
            float p1 = __expf(sacc[nj][1] - mrun[0]);
            float p2 = __expf(sacc[nj][2] - mrun[1]);
            float p3 = __expf(sacc[nj][3] - mrun[1]);
            sacc[nj][0] = p0; sacc[nj][1] = p1;
            sacc[nj][2] = p2; sacc[nj][3] = p3;
            psum[0] += p0 + p1;
            psum[1] += p2 + p3;
        }
#pragma unroll
        for (int r = 0; r < 2; r++) {
            psum[r] += __shfl_xor_sync(0xFFFFFFFFu, psum[r], 1);
            psum[r] += __shfl_xor_sync(0xFFFFFFFFu, psum[r], 2);
            lrun[r] = lrun[r] * corr[r] + psum[r];
        }
#pragma unroll
        for (int dn = 0; dn < 8; dn++) {
            o[dn][0] *= corr[0]; o[dn][1] *= corr[0];
            o[dn][2] *= corr[1]; o[dn][3] *= corr[1];
        }

        // ---- repack P -> A-frags ----
        uint32_t ph[4][4], pl[4][4];
#pragma unroll
        for (int ks = 0; ks < 4; ks++) {
            const float* c0 = sacc[2 * ks];
            const float* c1 = sacc[2 * ks + 1];
            split2(c0[0], c0[1], ph[ks][0], pl[ks][0]);
            split2(c0[2], c0[3], ph[ks][1], pl[ks][1]);
            split2(c1[0], c1[1], ph[ks][2], pl[ks][2]);
            split2(c1[2], c1[3], ph[ks][3], pl[ks][3]);
        }

        // ---- O += P V ----
#pragma unroll
        for (int ks = 0; ks < 4; ks++) {
            uint32_t vbh[8][2], vbl[8][2];
#pragma unroll
            for (int p = 0; p < 4; p++) {
                uint32_t off = (uint32_t)(((ks * 16 + v_row) * FLDV) + p * 16 + v_col) * 2;
                uint32_t t[4];
                ldsm_x4_t(t, sVh + off);
                vbh[2 * p][0] = t[0]; vbh[2 * p][1] = t[1];
                vbh[2 * p + 1][0] = t[2]; vbh[2 * p + 1][1] = t[3];
                ldsm_x4_t(t, sVl + off);
                vbl[2 * p][0] = t[0]; vbl[2 * p][1] = t[1];
                vbl[2 * p + 1][0] = t[2]; vbl[2 * p + 1][1] = t[3];
            }
#pragma unroll
            for (int dn = 0; dn < 8; dn++) {
                mma16816(o[dn], ph[ks], vbh[dn]);
                mma16816(o[dn], pl[ks], vbh[dn]);
                mma16816(o[dn], ph[ks], vbl[dn]);
            }
        }
        __syncthreads();
    }

    // ---- finalize + write ctx [B,S,H] ----
    float inv0 = 1.0f / lrun[0];
    float inv1 = 1.0f / lrun[1];
#pragma unroll
    for (int dn = 0; dn < 8; dn++) {
        int d = h * HD_ + dn * 8 + t2;
        int m0g = q0 + warp * 16 + g;
        float* dst0 = &ctx[((size_t)b * S_ + m0g) * H_ + d];
        float* dst1 = &ctx[((size_t)b * S_ + m0g + 8) * H_ + d];
        *(float2*)dst0 = make_float2(o[dn][0] * inv0, o[dn][1] * inv0);
        *(float2*)dst1 = make_float2(o[dn][2] * inv1, o[dn][3] * inv1);
    }
}

// ---------------- layernorm (one block per row) --------------------------
__global__ __launch_bounds__(256) void layernorm_k(
    const float* __restrict__ hin, const float* __restrict__ gamma,
    const float* __restrict__ beta, float* __restrict__ out)
{
    const int row = blockIdx.x;
    const int t = threadIdx.x;
    const float* hp = hin + (size_t)row * H_;
    float* op = out + (size_t)row * H_;

    float4 x4 = ((const float4*)hp)[t];
    float sum = x4.x + x4.y + x4.z + x4.w;
    float sq  = x4.x * x4.x + x4.y * x4.y + x4.z * x4.z + x4.w * x4.w;

#pragma unroll
    for (int off = 16; off > 0; off >>= 1) {
        sum += __shfl_xor_sync(0xFFFFFFFFu, sum, off);
        sq  += __shfl_xor_sync(0xFFFFFFFFu, sq,  off);
    }
    __shared__ float ssum[8], ssq[8];
    const int wid = t >> 5, lid = t & 31;
    if (lid == 0) { ssum[wid] = sum; ssq[wid] = sq; }
    __syncthreads();
    if (wid == 0) {
        float a = (lid < 8) ? ssum[lid] : 0.f;
        float b = (lid < 8) ? ssq[lid]  : 0.f;
#pragma unroll
        for (int off = 4; off > 0; off >>= 1) {
            a += __shfl_xor_sync(0xFFFFFFFFu, a, off);
            b += __shfl_xor_sync(0xFFFFFFFFu, b, off);
        }
        if (lid == 0) { ssum[0] = a; ssq[0] = b; }
    }
    __syncthreads();
    const float mean = ssum[0] * (1.0f / H_);
    const float var  = ssq[0] * (1.0f / H_) - mean * mean;
    const float rstd = rsqrtf(var + 1e-12f);

    float4 g4 = ((const float4*)gamma)[t];
    float4 b4 = ((const float4*)beta)[t];
    float4 o4;
    o4.x = g4.x * (x4.x - mean) * rstd + b4.x;
    o4.y = g4.y * (x4.y - mean) * rstd + b4.y;
    o4.z = g4.z * (x4.z - mean) * rstd + b4.z;
    o4.w = g4.w * (x4.w - mean) * rstd + b4.w;
    ((float4*)op)[t] = o4;
}

// ---------------- launch ----------------
extern "C" void kernel_launch(void* const* d_in, const int* in_sizes, int n_in,
                              void* d_out, int out_size)
{
    const float* x     = (const float*)d_in[0];
    const float* wq    = (const float*)d_in[1];
    const float* bq    = (const float*)d_in[2];
    const float* wk    = (const float*)d_in[3];
    const float* bk    = (const float*)d_in[4];
    const float* wv    = (const float*)d_in[5];
    const float* bv    = (const float*)d_in[6];
    const float* wo    = (const float*)d_in[7];
    const float* bo    = (const float*)d_in[8];
    const float* gamma = (const float*)d_in[9];
    const float* beta  = (const float*)d_in[10];

    float *q, *k, *v, *ctx, *hbuf;
    cudaGetSymbolAddress((void**)&q,    g_q);
    cudaGetSymbolAddress((void**)&k,    g_k);
    cudaGetSymbolAddress((void**)&v,    g_v);
    cudaGetSymbolAddress((void**)&ctx,  g_ctx);
    cudaGetSymbolAddress((void**)&hbuf, g_h);

    dim3 tb(256);

    // fused QKV projections (gridDim.z picks the weight set)
    gemm_bf16x3<<<dim3(H_ / BN, MTOT / BM, 3), tb>>>(
        x, wq, wk, wv, bq, bk, bv, q, k, v, nullptr, 1);

    // flash attention: 128 queries/CTA, 256 threads
    flash_mma<<<dim3(S_ / 128, NH_, B_), 256>>>(q, k, v, ctx);

    // output projection + residual
    gemm_bf16x3<<<dim3(H_ / BN, MTOT / BM, 1), tb>>>(
        ctx, wo, wo, wo, bo, bo, bo, hbuf, hbuf, hbuf, x, 0);

    layernorm_k<<<MTOT, 256>>>(hbuf, gamma, beta, (float*)d_out);
}

// round 10
// speedup vs baseline: 1.1725x; 1.0143x over previous
#include <cuda_runtime.h>
#include <cuda_bf16.h>
#include <math.h>
#include <stdint.h>

#define B_   4
#define S_   2048
#define H_   1024
#define NH_  16
#define HD_  64
#define MTOT (B_ * S_)   // 8192

// ---------------- scratch (no allocs allowed) ----------------
__device__ float g_q[(size_t)B_ * NH_ * S_ * HD_];    // [B,NH,S,HD]
__device__ float g_k[(size_t)B_ * NH_ * S_ * HD_];
__device__ float g_v[(size_t)B_ * NH_ * S_ * HD_];
__device__ float g_ctx[(size_t)B_ * S_ * H_];         // [B,S,H]
__device__ float g_h[(size_t)B_ * S_ * H_];           // pre-LN

// ---------------- common PTX helpers ----------------
__device__ __forceinline__ void mma16816(float* c, const uint32_t* a, const uint32_t* b) {
    asm volatile(
        "mma.sync.aligned.m16n8k16.row.col.f32.bf16.bf16.f32 "
        "{%0,%1,%2,%3}, {%4,%5,%6,%7}, {%8,%9}, {%0,%1,%2,%3};\n"
        : "+f"(c[0]), "+f"(c[1]), "+f"(c[2]), "+f"(c[3])
        : "r"(a[0]), "r"(a[1]), "r"(a[2]), "r"(a[3]), "r"(b[0]), "r"(b[1]));
}
__device__ __forceinline__ void ldsm_x4(uint32_t* r, uint32_t addr) {
    asm volatile(
        "ldmatrix.sync.aligned.m8n8.x4.shared.b16 {%0,%1,%2,%3}, [%4];\n"
        : "=r"(r[0]), "=r"(r[1]), "=r"(r[2]), "=r"(r[3]) : "r"(addr));
}
__device__ __forceinline__ void ldsm_x4_t(uint32_t* r, uint32_t addr) {
    asm volatile(
        "ldmatrix.sync.aligned.m8n8.x4.trans.shared.b16 {%0,%1,%2,%3}, [%4];\n"
        : "=r"(r[0]), "=r"(r[1]), "=r"(r[2]), "=r"(r[3]) : "r"(addr));
}
// split two floats -> packed bf16x2 hi and lo
__device__ __forceinline__ void split2(float x, float y, uint32_t& hi, uint32_t& lo) {
    __nv_bfloat16 hx = __float2bfloat16(x), hy = __float2bfloat16(y);
    __nv_bfloat16 lx = __float2bfloat16(x - __bfloat162float(hx));
    __nv_bfloat16 ly = __float2bfloat16(y - __bfloat162float(hy));
    __nv_bfloat162 h2 = __halves2bfloat162(hx, hy);
    __nv_bfloat162 l2 = __halves2bfloat162(lx, ly);
    hi = *(uint32_t*)&h2;
    lo = *(uint32_t*)&l2;
}

// ============================================================
//  bf16x3 tensor-core GEMM, double-buffered dynamic smem.
//  C[M,N] = A[M,K] * W[N,K]^T + bias ; gridDim.z = QKV select.
// ============================================================
#define BM 128
#define BN 128
#define BK 32
#define LDS_PAD 8
#define LDK (BK + LDS_PAD)     // 40 halves = 80 B row stride (16B-aligned)

// dynamic smem layout (bytes): Ah | Al | Bh | Bl, each 2 buffers of BM*LDK bf16
#define G_ARR (2 * BM * LDK * 2)          // 20480 B per array (both buffers)
#define GEMM_SMEM (4 * G_ARR)             // 81920 B

__global__ __launch_bounds__(256) void gemm_bf16x3(
    const float* __restrict__ A,
    const float* __restrict__ W0, const float* __restrict__ W1, const float* __restrict__ W2,
    const float* __restrict__ bias0, const float* __restrict__ bias1, const float* __restrict__ bias2,
    float* __restrict__ C0, float* __restrict__ C1, float* __restrict__ C2,
    const float* __restrict__ resid, int qkv_layout)
{
    extern __shared__ char smem[];
    const int K = H_, N = H_;
    const int z = blockIdx.z;
    const float* W    = (z == 0) ? W0 : (z == 1) ? W1 : W2;
    const float* bias = (z == 0) ? bias0 : (z == 1) ? bias1 : bias2;
    float*       C    = (z == 0) ? C0 : (z == 1) ? C1 : C2;

    __nv_bfloat16* Ah = (__nv_bfloat16*)(smem);
    __nv_bfloat16* Al = (__nv_bfloat16*)(smem + G_ARR);
    __nv_bfloat16* Bh = (__nv_bfloat16*)(smem + 2 * G_ARR);
    __nv_bfloat16* Bl = (__nv_bfloat16*)(smem + 3 * G_ARR);

    const int tid  = threadIdx.x;
    const int warp = tid >> 5;
    const int lane = tid & 31;
    const int rowBase = blockIdx.y * BM;
    const int colBase = blockIdx.x * BN;

    const int m0 = (warp >> 1) * 32;
    const int n0 = (warp & 1) * 64;

    const int lrow = tid >> 1;
    const int lcol = (tid & 1) * 16;
    const float* Ag = A + (size_t)(rowBase + lrow) * K + lcol;
    const float* Wg = W + (size_t)(colBase + lrow) * K + lcol;

    const int a_row = m0 + ((lane >> 3) & 1) * 8 + (lane & 7);
    const int a_col = ((lane >> 4) & 1) * 8;
    const int b_row = n0 + ((lane >> 4) & 1) * 8 + (lane & 7);
    const int b_col = ((lane >> 3) & 1) * 8;

    const uint32_t bufStrideA = (uint32_t)(BM * LDK * 2);   // bytes per buffer
    const uint32_t sAh = (uint32_t)__cvta_generic_to_shared(Ah);
    const uint32_t sAl = (uint32_t)__cvta_generic_to_shared(Al);
    const uint32_t sBh = (uint32_t)__cvta_generic_to_shared(Bh);
    const uint32_t sBl = (uint32_t)__cvta_generic_to_shared(Bl);

    float acc[2][8][4];
#pragma unroll
    for (int i = 0; i < 2; i++)
#pragma unroll
        for (int j = 0; j < 8; j++)
#pragma unroll
            for (int r = 0; r < 4; r++) acc[i][j][r] = 0.f;

    float4 ra[4], rb[4];
    // prologue: fetch + store tile 0 into buffer 0
#pragma unroll
    for (int v = 0; v < 4; v++) {
        ra[v] = *(const float4*)(Ag + v * 4);
        rb[v] = *(const float4*)(Wg + v * 4);
    }
    {
        uint32_t ahp[8], alp[8], bhp[8], blp[8];
#pragma unroll
        for (int v = 0; v < 4; v++) {
            const float* fa = (const float*)&ra[v];
            const float* fb = (const float*)&rb[v];
            split2(fa[0], fa[1], ahp[2 * v], alp[2 * v]);
            split2(fa[2], fa[3], ahp[2 * v + 1], alp[2 * v + 1]);
            split2(fb[0], fb[1], bhp[2 * v], blp[2 * v]);
            split2(fb[2], fb[3], bhp[2 * v + 1], blp[2 * v + 1]);
        }
        const int eo = lrow * LDK + lcol;
        float4* dAh = (float4*)(Ah + eo);
        float4* dAl = (float4*)(Al + eo);
        float4* dBh = (float4*)(Bh + eo);
        float4* dBl = (float4*)(Bl + eo);
        dAh[0] = ((float4*)ahp)[0]; dAh[1] = ((float4*)ahp)[1];
        dAl[0] = ((float4*)alp)[0]; dAl[1] = ((float4*)alp)[1];
        dBh[0] = ((float4*)bhp)[0]; dBh[1] = ((float4*)bhp)[1];
        dBl[0] = ((float4*)blp)[0]; dBl[1] = ((float4*)blp)[1];
    }
    __syncthreads();

    int p = 0;
    for (int kt = 0; kt < K; kt += BK) {
        const bool hasNext = (kt + BK < K);
        // prefetch next tile into regs (LDGs fly during MMA)
        if (hasNext) {
#pragma unroll
            for (int v = 0; v < 4; v++) {
                ra[v] = *(const float4*)(Ag + kt + BK + v * 4);
                rb[v] = *(const float4*)(Wg + kt + BK + v * 4);
            }
        }

        const uint32_t bufOff = (uint32_t)p * bufStrideA;
#pragma unroll
        for (int ks = 0; ks < 2; ks++) {
            const int kb = ks * 16;
            uint32_t ah[2][4], al[2][4], bh[8][2], bl[8][2];
#pragma unroll
            for (int mi = 0; mi < 2; mi++) {
                uint32_t off = bufOff + (uint32_t)(((a_row + mi * 16) * LDK) + kb + a_col) * 2;
                ldsm_x4(ah[mi], sAh + off);
                ldsm_x4(al[mi], sAl + off);
            }
#pragma unroll
            for (int pq = 0; pq < 4; pq++) {
                uint32_t off = bufOff + (uint32_t)(((b_row + pq * 16) * LDK) + kb + b_col) * 2;
                uint32_t t[4];
                ldsm_x4(t, sBh + off);
                bh[2 * pq][0] = t[0]; bh[2 * pq][1] = t[1];
                bh[2 * pq + 1][0] = t[2]; bh[2 * pq + 1][1] = t[3];
                ldsm_x4(t, sBl + off);
                bl[2 * pq][0] = t[0]; bl[2 * pq][1] = t[1];
                bl[2 * pq + 1][0] = t[2]; bl[2 * pq + 1][1] = t[3];
            }
#pragma unroll
            for (int nj = 0; nj < 8; nj++)
#pragma unroll
                for (int mi = 0; mi < 2; mi++) {
                    mma16816(acc[mi][nj], ah[mi], bh[nj]);
                    mma16816(acc[mi][nj], ah[mi], bl[nj]);
                    mma16816(acc[mi][nj], al[mi], bh[nj]);
                }
        }

        // store next tile into the other buffer (no race with in-flight reads)
        if (hasNext) {
            uint32_t ahp[8], alp[8], bhp[8], blp[8];
#pragma unroll
            for (int v = 0; v < 4; v++) {
                const float* fa = (const float*)&ra[v];
                const float* fb = (const float*)&rb[v];
                split2(fa[0], fa[1], ahp[2 * v], alp[2 * v]);
                split2(fa[2], fa[3], ahp[2 * v + 1], alp[2 * v + 1]);
                split2(fb[0], fb[1], bhp[2 * v], blp[2 * v]);
                split2(fb[2], fb[3], bhp[2 * v + 1], blp[2 * v + 1]);
            }
            const int eo = (p ^ 1) * (BM * LDK) + lrow * LDK + lcol;
            float4* dAh = (float4*)(Ah + eo);
            float4* dAl = (float4*)(Al + eo);
            float4* dBh = (float4*)(Bh + eo);
            float4* dBl = (float4*)(Bl + eo);
            dAh[0] = ((float4*)ahp)[0]; dAh[1] = ((float4*)ahp)[1];
            dAl[0] = ((float4*)alp)[0]; dAl[1] = ((float4*)alp)[1];
            dBh[0] = ((float4*)bhp)[0]; dBh[1] = ((float4*)bhp)[1];
            dBl[0] = ((float4*)blp)[0]; dBl[1] = ((float4*)blp)[1];
        }
        __syncthreads();
        p ^= 1;
    }

    const int g  = lane >> 2;
    const int t2 = (lane & 3) * 2;
#pragma unroll
    for (int mi = 0; mi < 2; mi++) {
#pragma unroll
        for (int nj = 0; nj < 8; nj++) {
            int n = colBase + n0 + nj * 8 + t2;
            float bia0 = bias[n], bia1 = bias[n + 1];
#pragma unroll
            for (int rr = 0; rr < 2; rr++) {
                int m = rowBase + m0 + mi * 16 + g + rr * 8;
                float v0 = acc[mi][nj][rr * 2 + 0] + bia0;
                float v1 = acc[mi][nj][rr * 2 + 1] + bia1;
                if (qkv_layout) {
                    int bb = m >> 11, ss = m & (S_ - 1);
                    int hh = n >> 6, dd = n & (HD_ - 1);
                    float2* dst = (float2*)&C[((((size_t)bb * NH_) + hh) * S_ + ss) * HD_ + dd];
                    *dst = make_float2(v0, v1);
                } else {
                    const float2 rs = *(const float2*)&resid[(size_t)m * N + n];
                    *(float2*)&C[(size_t)m * N + n] = make_float2(v0 + rs.x, v1 + rs.y);
                }
            }
        }
    }
}

// ============================================================
//  MMA flash attention (bf16x3), 128 q x 64 kv tiles,
//  256 threads, double-buffered dynamic smem, reg prefetch.
// ============================================================
#define FLDV 72   // padded row stride (halves) = 144 B; conflict-free STS.128 + ldsm
#define F_ARR (2 * 64 * FLDV * 2)          // 18432 B per array (both buffers)
#define FLASH_SMEM (4 * F_ARR)             // 73728 B

__global__ __launch_bounds__(256) void flash_mma(
    const float* __restrict__ Q, const float* __restrict__ Kg,
    const float* __restrict__ Vg, float* __restrict__ ctx)
{
    extern __shared__ char smem[];
    __nv_bfloat16* Kh = (__nv_bfloat16*)(smem);
    __nv_bfloat16* Kl = (__nv_bfloat16*)(smem + F_ARR);
    __nv_bfloat16* Vh = (__nv_bfloat16*)(smem + 2 * F_ARR);
    __nv_bfloat16* Vl = (__nv_bfloat16*)(smem + 3 * F_ARR);

    const int b = blockIdx.z;
    const int h = blockIdx.y;
    const int tid  = threadIdx.x;
    const int warp = tid >> 5;
    const int lane = tid & 31;
    const int q0 = blockIdx.x * 128;

    const size_t headBase = (((size_t)b * NH_ + h) * S_) * HD_;
    const float* qbase = Q  + headBase;
    const float* kbase = Kg + headBase;
    const float* vbase = Vg + headBase;

    // cooperative K/V load mapping: thread t -> row t>>2, cols (t&3)*16..+15
    const int lrow = tid >> 2;
    const int lcol = (tid & 3) * 16;

    const int b_row = ((lane >> 4) & 1) * 8 + (lane & 7);
    const int b_col = ((lane >> 3) & 1) * 8;
    const int v_row = ((lane >> 3) & 1) * 8 + (lane & 7);
    const int v_col = ((lane >> 4) & 1) * 8;

    const uint32_t bufStride = (uint32_t)(64 * FLDV * 2);   // bytes per buffer
    const uint32_t sKh = (uint32_t)__cvta_generic_to_shared(Kh);
    const uint32_t sKl = (uint32_t)__cvta_generic_to_shared(Kl);
    const uint32_t sVh = (uint32_t)__cvta_generic_to_shared(Vh);
    const uint32_t sVl = (uint32_t)__cvta_generic_to_shared(Vl);

    const int g  = lane >> 2;        // C/A-frag row group
    const int t2 = (lane & 3) * 2;   // C/A-frag col pair

    // ---- Q directly from gmem into A-fragments (scale folded) ----
    uint32_t qh[4][4], ql[4][4];
    {
        const float* qr0 = qbase + (size_t)(q0 + warp * 16 + g) * HD_;
        const float* qr1 = qr0 + 8 * HD_;
#pragma unroll
        for (int ks = 0; ks < 4; ks++) {
            int c = ks * 16 + t2;
            float2 f00 = *(const float2*)(qr0 + c);
            float2 f10 = *(const float2*)(qr1 + c);
            float2 f01 = *(const float2*)(qr0 + c + 8);
            float2 f11 = *(const float2*)(qr1 + c + 8);
            split2(f00.x * 0.125f, f00.y * 0.125f, qh[ks][0], ql[ks][0]);
            split2(f10.x * 0.125f, f10.y * 0.125f, qh[ks][1], ql[ks][1]);
            split2(f01.x * 0.125f, f01.y * 0.125f, qh[ks][2], ql[ks][2]);
            split2(f11.x * 0.125f, f11.y * 0.125f, qh[ks][3], ql[ks][3]);
        }
    }

    float o[8][4];
#pragma unroll
    for (int dn = 0; dn < 8; dn++)
#pragma unroll
        for (int e = 0; e < 4; e++) o[dn][e] = 0.f;
    float mrun[2] = {-1e30f, -1e30f};
    float lrun[2] = {0.f, 0.f};

    // ---- prologue: tile 0 -> regs -> buffer 0 ----
    float4 kf[4], vf[4];
    {
        const float* kg = kbase + (size_t)lrow * HD_ + lcol;
        const float* vg = vbase + (size_t)lrow * HD_ + lcol;
#pragma unroll
        for (int i = 0; i < 4; i++) {
            kf[i] = *(const float4*)(kg + i * 4);
            vf[i] = *(const float4*)(vg + i * 4);
        }
        uint32_t khp[8], klp[8], vhp[8], vlp[8];
#pragma unroll
        for (int i = 0; i < 4; i++) {
            split2(kf[i].x, kf[i].y, khp[2 * i], klp[2 * i]);
            split2(kf[i].z, kf[i].w, khp[2 * i + 1], klp[2 * i + 1]);
            split2(vf[i].x, vf[i].y, vhp[2 * i], vlp[2 * i]);
            split2(vf[i].z, vf[i].w, vhp[2 * i + 1], vlp[2 * i + 1]);
        }
        const int eo = lrow * FLDV + lcol;
        float4* dKh = (float4*)(Kh + eo);
        float4* dKl = (float4*)(Kl + eo);
        float4* dVh = (float4*)(Vh + eo);
        float4* dVl = (float4*)(Vl + eo);
        dKh[0] = ((float4*)khp)[0]; dKh[1] = ((float4*)khp)[1];
        dKl[0] = ((float4*)klp)[0]; dKl[1] = ((float4*)klp)[1];
        dVh[0] = ((float4*)vhp)[0]; dVh[1] = ((float4*)vhp)[1];
        dVl[0] = ((float4*)vlp)[0]; dVl[1] = ((float4*)vlp)[1];
    }
    __syncthreads();

    int p = 0;
    for (int j0 = 0; j0 < S_; j0 += 64) {
        const bool hasNext = (j0 + 64 < S_);
        // ---- prefetch next tile into regs ----
        if (hasNext) {
            const float* kg = kbase + (size_t)(j0 + 64 + lrow) * HD_ + lcol;
            const float* vg = vbase + (size_t)(j0 + 64 + lrow) * HD_ + lcol;
#pragma unroll
            for (int i = 0; i < 4; i++) {
                kf[i] = *(const float4*)(kg + i * 4);
                vf[i] = *(const float4*)(vg + i * 4);
            }
        }

        const uint32_t bufOff = (uint32_t)p * bufStride;

        // ---- S = Q K^T ----
        float sacc[8][4];
#pragma unroll
        for (int nj = 0; nj < 8; nj++)
#pragma unroll
            for (int e = 0; e < 4; e++) sacc[nj][e] = 0.f;

#pragma unroll
        for (int ks = 0; ks < 4; ks++) {
            uint32_t bh[8][2], bl[8][2];
#pragma unroll
            for (int pq = 0; pq < 4; pq++) {
                uint32_t off = bufOff + (uint32_t)(((pq * 16 + b_row) * FLDV) + ks * 16 + b_col) * 2;
                uint32_t t[4];
                ldsm_x4(t, sKh + off);
                bh[2 * pq][0] = t[0]; bh[2 * pq][1] = t[1];
                bh[2 * pq + 1][0] = t[2]; bh[2 * pq + 1][1] = t[3];
                ldsm_x4(t, sKl + off);
                bl[2 * pq][0] = t[0]; bl[2 * pq][1] = t[1];
                bl[2 * pq + 1][0] = t[2]; bl[2 * pq + 1][1] = t[3];
            }
#pragma unroll
            for (int nj = 0; nj < 8; nj++) {
                mma16816(sacc[nj], qh[ks], bh[nj]);
                mma16816(sacc[nj], ql[ks], bh[nj]);
                mma16816(sacc[nj], qh[ks], bl[nj]);
            }
        }

        // ---- online softmax (rows g and g+8 per thread) ----
        float mloc[2] = {-1e30f, -1e30f};
#pragma unroll
        for (int nj = 0; nj < 8; nj++) {
            mloc[0] = fmaxf(mloc[0], fmaxf(sacc[nj][0], sacc[nj][1]));
            mloc[1] = fmaxf(mloc[1], fmaxf(sacc[nj][2], sacc[nj][3]));
        }
#pragma unroll
        for (int r = 0; r < 2; r++) {
            mloc[r] = fmaxf(mloc[r], __shfl_xor_sync(0xFFFFFFFFu, mloc[r], 1));
            mloc[r] = fmaxf(mloc[r], __shfl_xor_sync(0xFFFFFFFFu, mloc[r], 2));
        }
        float corr[2];
#pragma unroll
        for (int r = 0; r < 2; r++) {
            float mnew = fmaxf(mrun[r], mloc[r]);
            corr[r] = __expf(mrun[r] - mnew);
            mrun[r] = mnew;
        }
        float psum[2] = {0.f, 0.f};
#pragma unroll
        for (int nj = 0; nj < 8; nj++) {
            float p0 = __expf(sacc[nj][0] - mrun[0]);
            float p1 = __expf(sacc[nj][1] - mrun[0]);
            float p2 = __expf(sacc[nj][2] - mrun[1]);
            float p3 = __expf(sacc[nj][3] - mrun[1]);
            sacc[nj][0] = p0; sacc[nj][1] = p1;
            sacc[nj][2] = p2; sacc[nj][3] = p3;
            psum[0] += p0 + p1;
            psum[1] += p2 + p3;
        }
#pragma unroll
        for (int r = 0; r < 2; r++) {
            psum[r] += __shfl_xor_sync(0xFFFFFFFFu, psum[r], 1);
            psum[r] += __shfl_xor_sync(0xFFFFFFFFu, psum[r], 2);
            lrun[r] = lrun[r] * corr[r] + psum[r];
        }
#pragma unroll
        for (int dn = 0; dn < 8; dn++) {
            o[dn][0] *= corr[0]; o[dn][1] *= corr[0];
            o[dn][2] *= corr[1]; o[dn][3] *= corr[1];
        }

        // ---- repack P -> A-frags ----
        uint32_t ph[4][4], pl[4][4];
#pragma unroll
        for (int ks = 0; ks < 4; ks++) {
            const float* c0 = sacc[2 * ks];
            const float* c1 = sacc[2 * ks + 1];
            split2(c0[0], c0[1], ph[ks][0], pl[ks][0]);
            split2(c0[2], c0[3], ph[ks][1], pl[ks][1]);
            split2(c1[0], c1[1], ph[ks][2], pl[ks][2]);
            split2(c1[2], c1[3], ph[ks][3], pl[ks][3]);
        }

        // ---- O += P V ----
#pragma unroll
        for (int ks = 0; ks < 4; ks++) {
            uint32_t vbh[8][2], vbl[8][2];
#pragma unroll
            for (int pq = 0; pq < 4; pq++) {
                uint32_t off = bufOff + (uint32_t)(((ks * 16 + v_row) * FLDV) + pq * 16 + v_col) * 2;
                uint32_t t[4];
                ldsm_x4_t(t, sVh + off);
                vbh[2 * pq][0] = t[0]; vbh[2 * pq][1] = t[1];
                vbh[2 * pq + 1][0] = t[2]; vbh[2 * pq + 1][1] = t[3];
                ldsm_x4_t(t, sVl + off);
                vbl[2 * pq][0] = t[0]; vbl[2 * pq][1] = t[1];
                vbl[2 * pq + 1][0] = t[2]; vbl[2 * pq + 1][1] = t[3];
            }
#pragma unroll
            for (int dn = 0; dn < 8; dn++) {
                mma16816(o[dn], ph[ks], vbh[dn]);
                mma16816(o[dn], pl[ks], vbh[dn]);
                mma16816(o[dn], ph[ks], vbl[dn]);
            }
        }

        // ---- store prefetched tile into the other buffer ----
        if (hasNext) {
            uint32_t khp[8], klp[8], vhp[8], vlp[8];
#pragma unroll
            for (int i = 0; i < 4; i++) {
                split2(kf[i].x, kf[i].y, khp[2 * i], klp[2 * i]);
                split2(kf[i].z, kf[i].w, khp[2 * i + 1], klp[2 * i + 1]);
                split2(vf[i].x, vf[i].y, vhp[2 * i], vlp[2 * i]);
                split2(vf[i].z, vf[i].w, vhp[2 * i + 1], vlp[2 * i + 1]);
            }
            const int eo = (p ^ 1) * (64 * FLDV) + lrow * FLDV + lcol;
            float4* dKh = (float4*)(Kh + eo);
            float4* dKl = (float4*)(Kl + eo);
            float4* dVh = (float4*)(Vh + eo);
            float4* dVl = (float4*)(Vl + eo);
            dKh[0] = ((float4*)khp)[0]; dKh[1] = ((float4*)khp)[1];
            dKl[0] = ((float4*)klp)[0]; dKl[1] = ((float4*)klp)[1];
            dVh[0] = ((float4*)vhp)[0]; dVh[1] = ((float4*)vhp)[1];
            dVl[0] = ((float4*)vlp)[0]; dVl[1] = ((float4*)vlp)[1];
        }
        __syncthreads();
        p ^= 1;
    }

    // ---- finalize + write ctx [B,S,H] ----
    float inv0 = 1.0f / lrun[0];
    float inv1 = 1.0f / lrun[1];
#pragma unroll
    for (int dn = 0; dn < 8; dn++) {
        int d = h * HD_ + dn * 8 + t2;
        int m0g = q0 + warp * 16 + g;
        float* dst0 = &ctx[((size_t)b * S_ + m0g) * H_ + d];
        float* dst1 = &ctx[((size_t)b * S_ + m0g + 8) * H_ + d];
        *(float2*)dst0 = make_float2(o[dn][0] * inv0, o[dn][1] * inv0);
        *(float2*)dst1 = make_float2(o[dn][2] * inv1, o[dn][3] * inv1);
    }
}

// ---------------- layernorm (one block per row) --------------------------
__global__ __launch_bounds__(256) void layernorm_k(
    const float* __restrict__ hin, const float* __restrict__ gamma,
    const float* __restrict__ beta, float* __restrict__ out)
{
    const int row = blockIdx.x;
    const int t = threadIdx.x;
    const float* hp = hin + (size_t)row * H_;
    float* op = out + (size_t)row * H_;

    float4 x4 = ((const float4*)hp)[t];
    float sum = x4.x + x4.y + x4.z + x4.w;
    float sq  = x4.x * x4.x + x4.y * x4.y + x4.z * x4.z + x4.w * x4.w;

#pragma unroll
    for (int off = 16; off > 0; off >>= 1) {
        sum += __shfl_xor_sync(0xFFFFFFFFu, sum, off);
        sq  += __shfl_xor_sync(0xFFFFFFFFu, sq,  off);
    }
    __shared__ float ssum[8], ssq[8];
    const int wid = t >> 5, lid = t & 31;
    if (lid == 0) { ssum[wid] = sum; ssq[wid] = sq; }
    __syncthreads();
    if (wid == 0) {
        float a = (lid < 8) ? ssum[lid] : 0.f;
        float b = (lid < 8) ? ssq[lid]  : 0.f;
#pragma unroll
        for (int off = 4; off > 0; off >>= 1) {
            a += __shfl_xor_sync(0xFFFFFFFFu, a, off);
            b += __shfl_xor_sync(0xFFFFFFFFu, b, off);
        }
        if (lid == 0) { ssum[0] = a; ssq[0] = b; }
    }
    __syncthreads();
    const float mean = ssum[0] * (1.0f / H_);
    const float var  = ssq[0] * (1.0f / H_) - mean * mean;
    const float rstd = rsqrtf(var + 1e-12f);

    float4 g4 = ((const float4*)gamma)[t];
    float4 b4 = ((const float4*)beta)[t];
    float4 o4;
    o4.x = g4.x * (x4.x - mean) * rstd + b4.x;
    o4.y = g4.y * (x4.y - mean) * rstd + b4.y;
    o4.z = g4.z * (x4.z - mean) * rstd + b4.z;
    o4.w = g4.w * (x4.w - mean) * rstd + b4.w;
    ((float4*)op)[t] = o4;
}

// ---------------- launch ----------------
extern "C" void kernel_launch(void* const* d_in, const int* in_sizes, int n_in,
                              void* d_out, int out_size)
{
    const float* x     = (const float*)d_in[0];
    const float* wq    = (const float*)d_in[1];
    const float* bq    = (const float*)d_in[2];
    const float* wk    = (const float*)d_in[3];
    const float* bk    = (const float*)d_in[4];
    const float* wv    = (const float*)d_in[5];
    const float* bv    = (const float*)d_in[6];
    const float* wo    = (const float*)d_in[7];
    const float* bo    = (const float*)d_in[8];
    const float* gamma = (const float*)d_in[9];
    const float* beta  = (const float*)d_in[10];

    float *q, *k, *v, *ctx, *hbuf;
    cudaGetSymbolAddress((void**)&q,    g_q);
    cudaGetSymbolAddress((void**)&k,    g_k);
    cudaGetSymbolAddress((void**)&v,    g_v);
    cudaGetSymbolAddress((void**)&ctx,  g_ctx);
    cudaGetSymbolAddress((void**)&hbuf, g_h);

    // opt in to large dynamic smem (host-side attr set; no allocation)
    cudaFuncSetAttribute(gemm_bf16x3,
                         cudaFuncAttributeMaxDynamicSharedMemorySize, GEMM_SMEM);
    cudaFuncSetAttribute(flash_mma,
                         cudaFuncAttributeMaxDynamicSharedMemorySize, FLASH_SMEM);

    dim3 tb(256);

    // fused QKV projections (gridDim.z picks the weight set)
    gemm_bf16x3<<<dim3(H_ / BN, MTOT / BM, 3), tb, GEMM_SMEM>>>(
        x, wq, wk, wv, bq, bk, bv, q, k, v, nullptr, 1);

    // flash attention: 128 queries/CTA, 256 threads
    flash_mma<<<dim3(S_ / 128, NH_, B_), 256, FLASH_SMEM>>>(q, k, v, ctx);

    // output projection + residual
    gemm_bf16x3<<<dim3(H_ / BN, MTOT / BM, 1), tb, GEMM_SMEM>>>(
        ctx, wo, wo, wo, bo, bo, bo, hbuf, hbuf, hbuf, x, 0);

    layernorm_k<<<MTOT, 256>>>(hbuf, gamma, beta, (float*)d_out);
}

// round 12
// speedup vs baseline: 1.2144x; 1.0358x over previous
#include <cuda_runtime.h>
#include <cuda_bf16.h>
#include <math.h>
#include <stdint.h>

#define B_   4
#define S_   2048
#define H_   1024
#define NH_  16
#define HD_  64
#define MTOT (B_ * S_)   // 8192
#define HEADN ((size_t)B_ * NH_ * S_ * HD_)

// ---------------- scratch (no allocs allowed) ----------------
__device__ __nv_bfloat16 g_xh[(size_t)MTOT * H_], g_xl[(size_t)MTOT * H_];
__device__ __nv_bfloat16 g_wqh[(size_t)H_ * H_], g_wql[(size_t)H_ * H_];
__device__ __nv_bfloat16 g_wkh[(size_t)H_ * H_], g_wkl[(size_t)H_ * H_];
__device__ __nv_bfloat16 g_wvh[(size_t)H_ * H_], g_wvl[(size_t)H_ * H_];
__device__ __nv_bfloat16 g_woh[(size_t)H_ * H_], g_wol[(size_t)H_ * H_];
__device__ __nv_bfloat16 g_qh[HEADN], g_ql[HEADN];
__device__ __nv_bfloat16 g_kh[HEADN], g_kl[HEADN];
__device__ __nv_bfloat16 g_vh[HEADN], g_vl[HEADN];
__device__ __nv_bfloat16 g_ch[(size_t)MTOT * H_], g_cl[(size_t)MTOT * H_];
__device__ float g_h[(size_t)MTOT * H_];            // pre-LN fp32

// ---------------- common PTX helpers ----------------
__device__ __forceinline__ void mma16816(float* c, const uint32_t* a, const uint32_t* b) {
    asm volatile(
        "mma.sync.aligned.m16n8k16.row.col.f32.bf16.bf16.f32 "
        "{%0,%1,%2,%3}, {%4,%5,%6,%7}, {%8,%9}, {%0,%1,%2,%3};\n"
        : "+f"(c[0]), "+f"(c[1]), "+f"(c[2]), "+f"(c[3])
        : "r"(a[0]), "r"(a[1]), "r"(a[2]), "r"(a[3]), "r"(b[0]), "r"(b[1]));
}
__device__ __forceinline__ void ldsm_x4(uint32_t* r, uint32_t addr) {
    asm volatile(
        "ldmatrix.sync.aligned.m8n8.x4.shared.b16 {%0,%1,%2,%3}, [%4];\n"
        : "=r"(r[0]), "=r"(r[1]), "=r"(r[2]), "=r"(r[3]) : "r"(addr));
}
__device__ __forceinline__ void ldsm_x4_t(uint32_t* r, uint32_t addr) {
    asm volatile(
        "ldmatrix.sync.aligned.m8n8.x4.trans.shared.b16 {%0,%1,%2,%3}, [%4];\n"
        : "=r"(r[0]), "=r"(r[1]), "=r"(r[2]), "=r"(r[3]) : "r"(addr));
}
__device__ __forceinline__ void split2(float x, float y, uint32_t& hi, uint32_t& lo) {
    __nv_bfloat16 hx = __float2bfloat16(x), hy = __float2bfloat16(y);
    __nv_bfloat16 lx = __float2bfloat16(x - __bfloat162float(hx));
    __nv_bfloat16 ly = __float2bfloat16(y - __bfloat162float(hy));
    __nv_bfloat162 h2 = __halves2bfloat162(hx, hy);
    __nv_bfloat162 l2 = __halves2bfloat162(lx, ly);
    hi = *(uint32_t*)&h2;
    lo = *(uint32_t*)&l2;
}

// ---------------- prep: split fp32 -> bf16 hi/lo ----------------
__global__ __launch_bounds__(256) void split_pre(
    const float4* __restrict__ src, uint2* __restrict__ dh,
    uint2* __restrict__ dl, int n4)
{
    int i = blockIdx.x * blockDim.x + threadIdx.x;
    if (i >= n4) return;
    float4 f = src[i];
    uint32_t h0, l0, h1, l1;
    split2(f.x, f.y, h0, l0);
    split2(f.z, f.w, h1, l1);
    dh[i] = make_uint2(h0, h1);
    dl[i] = make_uint2(l0, l1);
}

// ============================================================
//  bf16x3 tensor-core GEMM, pre-split inputs, double-buffered.
//  C[M,N] = A[M,K] * W[N,K]^T + bias ; gridDim.z = QKV select.
// ============================================================
#define BM 128
#define BN 128
#define BK 32
#define LDS_PAD 8
#define LDK (BK + LDS_PAD)      // 40 halves = 80 B row stride
#define G_ARR (2 * BM * LDK * 2)          // 20480 B per array (2 buffers)
#define GEMM_SMEM (4 * G_ARR)             // 81920 B

__global__ __launch_bounds__(256) void gemm_pre(
    const __nv_bfloat16* __restrict__ Ah, const __nv_bfloat16* __restrict__ Al,
    const __nv_bfloat16* __restrict__ Wh0, const __nv_bfloat16* __restrict__ Wl0,
    const __nv_bfloat16* __restrict__ Wh1, const __nv_bfloat16* __restrict__ Wl1,
    const __nv_bfloat16* __restrict__ Wh2, const __nv_bfloat16* __restrict__ Wl2,
    const float* __restrict__ bias0, const float* __restrict__ bias1, const float* __restrict__ bias2,
    __nv_bfloat16* __restrict__ Oh0, __nv_bfloat16* __restrict__ Ol0,
    __nv_bfloat16* __restrict__ Oh1, __nv_bfloat16* __restrict__ Ol1,
    __nv_bfloat16* __restrict__ Oh2, __nv_bfloat16* __restrict__ Ol2,
    float* __restrict__ Cf, const float* __restrict__ resid, int qkv_layout)
{
    extern __shared__ char smem[];
    const int K = H_;
    const int z = blockIdx.z;
    const __nv_bfloat16* Wh = (z == 0) ? Wh0 : (z == 1) ? Wh1 : Wh2;
    const __nv_bfloat16* Wl = (z == 0) ? Wl0 : (z == 1) ? Wl1 : Wl2;
    const float* bias = (z == 0) ? bias0 : (z == 1) ? bias1 : bias2;
    __nv_bfloat16* Oh = (z == 0) ? Oh0 : (z == 1) ? Oh1 : Oh2;
    __nv_bfloat16* Ol = (z == 0) ? Ol0 : (z == 1) ? Ol1 : Ol2;
    const float scale = (qkv_layout && z == 0) ? 0.125f : 1.0f;

    __nv_bfloat16* sA_h = (__nv_bfloat16*)(smem);
    __nv_bfloat16* sA_l = (__nv_bfloat16*)(smem + G_ARR);
    __nv_bfloat16* sB_h = (__nv_bfloat16*)(smem + 2 * G_ARR);
    __nv_bfloat16* sB_l = (__nv_bfloat16*)(smem + 3 * G_ARR);

    const int tid  = threadIdx.x;
    const int warp = tid >> 5;
    const int lane = tid & 31;
    const int rowBase = blockIdx.y * BM;
    const int colBase = blockIdx.x * BN;

    const int m0 = (warp >> 1) * 32;
    const int n0 = (warp & 1) * 64;

    const int lrow = tid >> 1;
    const int lcol = (tid & 1) * 16;
    const __nv_bfloat16* Agh = Ah + (size_t)(rowBase + lrow) * K + lcol;
    const __nv_bfloat16* Agl = Al + (size_t)(rowBase + lrow) * K + lcol;
    const __nv_bfloat16* Wgh = Wh + (size_t)(colBase + lrow) * K + lcol;
    const __nv_bfloat16* Wgl = Wl + (size_t)(colBase + lrow) * K + lcol;

    const int a_row = m0 + ((lane >> 3) & 1) * 8 + (lane & 7);
    const int a_col = ((lane >> 4) & 1) * 8;
    const int b_row = n0 + ((lane >> 4) & 1) * 8 + (lane & 7);
    const int b_col = ((lane >> 3) & 1) * 8;

    const uint32_t bufStride = (uint32_t)(BM * LDK * 2);
    const uint32_t sAhU = (uint32_t)__cvta_generic_to_shared(sA_h);
    const uint32_t sAlU = (uint32_t)__cvta_generic_to_shared(sA_l);
    const uint32_t sBhU = (uint32_t)__cvta_generic_to_shared(sB_h);
    const uint32_t sBlU = (uint32_t)__cvta_generic_to_shared(sB_l);

    float acc[2][8][4];
#pragma unroll
    for (int i = 0; i < 2; i++)
#pragma unroll
        for (int j = 0; j < 8; j++)
#pragma unroll
            for (int r = 0; r < 4; r++) acc[i][j][r] = 0.f;

    uint4 rah[2], ral[2], rbh[2], rbl[2];
    // prologue: tile 0 -> regs -> buffer 0
    rah[0] = *(const uint4*)(Agh);     rah[1] = *(const uint4*)(Agh + 8);
    ral[0] = *(const uint4*)(Agl);     ral[1] = *(const uint4*)(Agl + 8);
    rbh[0] = *(const uint4*)(Wgh);     rbh[1] = *(const uint4*)(Wgh + 8);
    rbl[0] = *(const uint4*)(Wgl);     rbl[1] = *(const uint4*)(Wgl + 8);
    {
        const int eo = lrow * LDK + lcol;
        *(uint4*)(sA_h + eo) = rah[0]; *(uint4*)(sA_h + eo + 8) = rah[1];
        *(uint4*)(sA_l + eo) = ral[0]; *(uint4*)(sA_l + eo + 8) = ral[1];
        *(uint4*)(sB_h + eo) = rbh[0]; *(uint4*)(sB_h + eo + 8) = rbh[1];
        *(uint4*)(sB_l + eo) = rbl[0]; *(uint4*)(sB_l + eo + 8) = rbl[1];
    }
    __syncthreads();

    int p = 0;
    for (int kt = 0; kt < K; kt += BK) {
        const bool hasNext = (kt + BK < K);
        if (hasNext) {
            rah[0] = *(const uint4*)(Agh + kt + BK);  rah[1] = *(const uint4*)(Agh + kt + BK + 8);
            ral[0] = *(const uint4*)(Agl + kt + BK);  ral[1] = *(const uint4*)(Agl + kt + BK + 8);
            rbh[0] = *(const uint4*)(Wgh + kt + BK);  rbh[1] = *(const uint4*)(Wgh + kt + BK + 8);
            rbl[0] = *(const uint4*)(Wgl + kt + BK);  rbl[1] = *(const uint4*)(Wgl + kt + BK + 8);
        }

        const uint32_t bufOff = (uint32_t)p * bufStride;
#pragma unroll
        for (int ks = 0; ks < 2; ks++) {
            const int kb = ks * 16;
            uint32_t ah[2][4], al[2][4], bh[8][2], bl[8][2];
#pragma unroll
            for (int mi = 0; mi < 2; mi++) {
                uint32_t off = bufOff + (uint32_t)(((a_row + mi * 16) * LDK) + kb + a_col) * 2;
                ldsm_x4(ah[mi], sAhU + off);
                ldsm_x4(al[mi], sAlU + off);
            }
#pragma unroll
            for (int pq = 0; pq < 4; pq++) {
                uint32_t off = bufOff + (uint32_t)(((b_row + pq * 16) * LDK) + kb + b_col) * 2;
                uint32_t t[4];
                ldsm_x4(t, sBhU + off);
                bh[2 * pq][0] = t[0]; bh[2 * pq][1] = t[1];
                bh[2 * pq + 1][0] = t[2]; bh[2 * pq + 1][1] = t[3];
                ldsm_x4(t, sBlU + off);
                bl[2 * pq][0] = t[0]; bl[2 * pq][1] = t[1];
                bl[2 * pq + 1][0] = t[2]; bl[2 * pq + 1][1] = t[3];
            }
#pragma unroll
            for (int nj = 0; nj < 8; nj++)
#pragma unroll
                for (int mi = 0; mi < 2; mi++) {
                    mma16816(acc[mi][nj], ah[mi], bh[nj]);
                    mma16816(acc[mi][nj], ah[mi], bl[nj]);
                    mma16816(acc[mi][nj], al[mi], bh[nj]);
                }
        }

        if (hasNext) {
            const int eo = (p ^ 1) * (BM * LDK) + lrow * LDK + lcol;
            *(uint4*)(sA_h + eo) = rah[0]; *(uint4*)(sA_h + eo + 8) = rah[1];
            *(uint4*)(sA_l + eo) = ral[0]; *(uint4*)(sA_l + eo + 8) = ral[1];
            *(uint4*)(sB_h + eo) = rbh[0]; *(uint4*)(sB_h + eo + 8) = rbh[1];
            *(uint4*)(sB_l + eo) = rbl[0]; *(uint4*)(sB_l + eo + 8) = rbl[1];
        }
        __syncthreads();
        p ^= 1;
    }

    const int g  = lane >> 2;
    const int t2 = (lane & 3) * 2;
#pragma unroll
    for (int mi = 0; mi < 2; mi++) {
#pragma unroll
        for (int nj = 0; nj < 8; nj++) {
            int n = colBase + n0 + nj * 8 + t2;
            float bia0 = bias[n], bia1 = bias[n + 1];
#pragma unroll
            for (int rr = 0; rr < 2; rr++) {
                int m = rowBase + m0 + mi * 16 + g + rr * 8;
                float v0 = acc[mi][nj][rr * 2 + 0] + bia0;
                float v1 = acc[mi][nj][rr * 2 + 1] + bia1;
                if (qkv_layout) {
                    v0 *= scale; v1 *= scale;
                    uint32_t hi, lo;
                    split2(v0, v1, hi, lo);
                    int bb = m >> 11, ss = m & (S_ - 1);
                    int hh = n >> 6, dd = n & (HD_ - 1);
                    size_t off = ((((size_t)bb * NH_) + hh) * S_ + ss) * HD_ + dd;
                    *(uint32_t*)&Oh[off] = hi;
                    *(uint32_t*)&Ol[off] = lo;
                } else {
                    const float2 rs = *(const float2*)&resid[(size_t)m * H_ + n];
                    *(float2*)&Cf[(size_t)m * H_ + n] = make_float2(v0 + rs.x, v1 + rs.y);
                }
            }
        }
    }
}

// ============================================================
//  MMA flash attention (bf16x3), 128 q x 64 kv tiles,
//  256 threads, pre-split bf16 inputs, double-buffered smem.
// ============================================================
#define FLDV 72
#define F_ARR (2 * 64 * FLDV * 2)
#define FLASH_SMEM (4 * F_ARR)

__global__ __launch_bounds__(256) void flash_mma(
    const __nv_bfloat16* __restrict__ Qh, const __nv_bfloat16* __restrict__ Ql,
    const __nv_bfloat16* __restrict__ Kgh, const __nv_bfloat16* __restrict__ Kgl,
    const __nv_bfloat16* __restrict__ Vgh, const __nv_bfloat16* __restrict__ Vgl,
    __nv_bfloat16* __restrict__ Ch, __nv_bfloat16* __restrict__ Cl)
{
    extern __shared__ char smem[];
    __nv_bfloat16* Kh = (__nv_bfloat16*)(smem);
    __nv_bfloat16* Kl = (__nv_bfloat16*)(smem + F_ARR);
    __nv_bfloat16* Vh = (__nv_bfloat16*)(smem + 2 * F_ARR);
    __nv_bfloat16* Vl = (__nv_bfloat16*)(smem + 3 * F_ARR);

    const int b = blockIdx.z;
    const int h = blockIdx.y;
    const int tid  = threadIdx.x;
    const int warp = tid >> 5;
    const int lane = tid & 31;
    const int q0 = blockIdx.x * 128;

    const size_t headBase = (((size_t)b * NH_ + h) * S_) * HD_;

    const int lrow = tid >> 2;
    const int lcol = (tid & 3) * 16;

    const int b_row = ((lane >> 4) & 1) * 8 + (lane & 7);
    const int b_col = ((lane >> 3) & 1) * 8;
    const int v_row = ((lane >> 3) & 1) * 8 + (lane & 7);
    const int v_col = ((lane >> 4) & 1) * 8;

    const uint32_t bufStride = (uint32_t)(64 * FLDV * 2);
    const uint32_t sKh = (uint32_t)__cvta_generic_to_shared(Kh);
    const uint32_t sKl = (uint32_t)__cvta_generic_to_shared(Kl);
    const uint32_t sVh = (uint32_t)__cvta_generic_to_shared(Vh);
    const uint32_t sVl = (uint32_t)__cvta_generic_to_shared(Vl);

    const int g  = lane >> 2;
    const int t2 = (lane & 3) * 2;

    // ---- Q fragments straight from pre-split gmem (already scaled) ----
    uint32_t qh[4][4], ql[4][4];
    {
        const __nv_bfloat16* qh0 = Qh + headBase + (size_t)(q0 + warp * 16 + g) * HD_;
        const __nv_bfloat16* qh1 = qh0 + 8 * HD_;
        const __nv_bfloat16* ql0 = Ql + headBase + (size_t)(q0 + warp * 16 + g) * HD_;
        const __nv_bfloat16* ql1 = ql0 + 8 * HD_;
#pragma unroll
        for (int ks = 0; ks < 4; ks++) {
            int c = ks * 16 + t2;
            qh[ks][0] = *(const uint32_t*)(qh0 + c);
            qh[ks][1] = *(const uint32_t*)(qh1 + c);
            qh[ks][2] = *(const uint32_t*)(qh0 + c + 8);
            qh[ks][3] = *(const uint32_t*)(qh1 + c + 8);
            ql[ks][0] = *(const uint32_t*)(ql0 + c);
            ql[ks][1] = *(const uint32_t*)(ql1 + c);
            ql[ks][2] = *(const uint32_t*)(ql0 + c + 8);
            ql[ks][3] = *(const uint32_t*)(ql1 + c + 8);
        }
    }

    float o[8][4];
#pragma unroll
    for (int dn = 0; dn < 8; dn++)
#pragma unroll
        for (int e = 0; e < 4; e++) o[dn][e] = 0.f;
    float mrun[2] = {-1e30f, -1e30f};
    float lrun[2] = {0.f, 0.f};

    // ---- prologue: tile 0 -> regs -> buffer 0 ----
    uint4 kh2[2], kl2[2], vh2[2], vl2[2];
    {
        const __nv_bfloat16* kgh = Kgh + headBase + (size_t)lrow * HD_ + lcol;
        const __nv_bfloat16* kgl = Kgl + headBase + (size_t)lrow * HD_ + lcol;
        const __nv_bfloat16* vgh = Vgh + headBase + (size_t)lrow * HD_ + lcol;
        const __nv_bfloat16* vgl = Vgl + headBase + (size_t)lrow * HD_ + lcol;
        kh2[0] = *(const uint4*)(kgh); kh2[1] = *(const uint4*)(kgh + 8);
        kl2[0] = *(const uint4*)(kgl); kl2[1] = *(const uint4*)(kgl + 8);
        vh2[0] = *(const uint4*)(vgh); vh2[1] = *(const uint4*)(vgh + 8);
        vl2[0] = *(const uint4*)(vgl); vl2[1] = *(const uint4*)(vgl + 8);
        const int eo = lrow * FLDV + lcol;
        *(uint4*)(Kh + eo) = kh2[0]; *(uint4*)(Kh + eo + 8) = kh2[1];
        *(uint4*)(Kl + eo) = kl2[0]; *(uint4*)(Kl + eo + 8) = kl2[1];
        *(uint4*)(Vh + eo) = vh2[0]; *(uint4*)(Vh + eo + 8) = vh2[1];
        *(uint4*)(Vl + eo) = vl2[0]; *(uint4*)(Vl + eo + 8) = vl2[1];
    }
    __syncthreads();

    int p = 0;
    for (int j0 = 0; j0 < S_; j0 += 64) {
        const bool hasNext = (j0 + 64 < S_);
        if (hasNext) {
            const __nv_bfloat16* kgh = Kgh + headBase + (size_t)(j0 + 64 + lrow) * HD_ + lcol;
            const __nv_bfloat16* kgl = Kgl + headBase + (size_t)(j0 + 64 + lrow) * HD_ + lcol;
            const __nv_bfloat16* vgh = Vgh + headBase + (size_t)(j0 + 64 + lrow) * HD_ + lcol;
            const __nv_bfloat16* vgl = Vgl + headBase + (size_t)(j0 + 64 + lrow) * HD_ + lcol;
            kh2[0] = *(const uint4*)(kgh); kh2[1] = *(const uint4*)(kgh + 8);
            kl2[0] = *(const uint4*)(kgl); kl2[1] = *(const uint4*)(kgl + 8);
            vh2[0] = *(const uint4*)(vgh); vh2[1] = *(const uint4*)(vgh + 8);
            vl2[0] = *(const uint4*)(vgl); vl2[1] = *(const uint4*)(vgl + 8);
        }

        const uint32_t bufOff = (uint32_t)p * bufStride;

        // ---- S = Q K^T ----
        float sacc[8][4];
#pragma unroll
        for (int nj = 0; nj < 8; nj++)
#pragma unroll
            for (int e = 0; e < 4; e++) sacc[nj][e] = 0.f;

#pragma unroll
        for (int ks = 0; ks < 4; ks++) {
            uint32_t bh[8][2], bl[8][2];
#pragma unroll
            for (int pq = 0; pq < 4; pq++) {
                uint32_t off = bufOff + (uint32_t)(((pq * 16 + b_row) * FLDV) + ks * 16 + b_col) * 2;
                uint32_t t[4];
                ldsm_x4(t, sKh + off);
                bh[2 * pq][0] = t[0]; bh[2 * pq][1] = t[1];
                bh[2 * pq + 1][0] = t[2]; bh[2 * pq + 1][1] = t[3];
                ldsm_x4(t, sKl + off);
                bl[2 * pq][0] = t[0]; bl[2 * pq][1] = t[1];
                bl[2 * pq + 1][0] = t[2]; bl[2 * pq + 1][1] = t[3];
            }
#pragma unroll
            for (int nj = 0; nj < 8; nj++) {
                mma16816(sacc[nj], qh[ks], bh[nj]);
                mma16816(sacc[nj], ql[ks], bh[nj]);
                mma16816(sacc[nj], qh[ks], bl[nj]);
            }
        }

        // ---- online softmax ----
        float mloc[2] = {-1e30f, -1e30f};
#pragma unroll
        for (int nj = 0; nj < 8; nj++) {
            mloc[0] = fmaxf(mloc[0], fmaxf(sacc[nj][0], sacc[nj][1]));
            mloc[1] = fmaxf(mloc[1], fmaxf(sacc[nj][2], sacc[nj][3]));
        }
#pragma unroll
        for (int r = 0; r < 2; r++) {
            mloc[r] = fmaxf(mloc[r], __shfl_xor_sync(0xFFFFFFFFu, mloc[r], 1));
            mloc[r] = fmaxf(mloc[r], __shfl_xor_sync(0xFFFFFFFFu, mloc[r], 2));
        }
        float corr[2];
#pragma unroll
        for (int r = 0; r < 2; r++) {
            float mnew = fmaxf(mrun[r], mloc[r]);
            corr[r] = __expf(mrun[r] - mnew);
            mrun[r] = mnew;
        }
        float psum[2] = {0.f, 0.f};
#pragma unroll
        for (int nj = 0; nj < 8; nj++) {
            float p0 = __expf(sacc[nj][0] - mrun[0]);
            float p1 = __expf(sacc[nj][1] - mrun[0]);
            float p2 = __expf(sacc[nj][2] - mrun[1]);
            float p3 = __expf(sacc[nj][3] - mrun[1]);
            sacc[nj][0] = p0; sacc[nj][1] = p1;
            sacc[nj][2] = p2; sacc[nj][3] = p3;
            psum[0] += p0 + p1;
            psum[1] += p2 + p3;
        }
#pragma unroll
        for (int r = 0; r < 2; r++) {
            psum[r] += __shfl_xor_sync(0xFFFFFFFFu, psum[r], 1);
            psum[r] += __shfl_xor_sync(0xFFFFFFFFu, psum[r], 2);
            lrun[r] = lrun[r] * corr[r] + psum[r];
        }
#pragma unroll
        for (int dn = 0; dn < 8; dn++) {
            o[dn][0] *= corr[0]; o[dn][1] *= corr[0];
            o[dn][2] *= corr[1]; o[dn][3] *= corr[1];
        }

        // ---- repack P -> A-frags (split kept: P is fp32-born) ----
        uint32_t ph[4][4], pl[4][4];
#pragma unroll
        for (int ks = 0; ks < 4; ks++) {
            const float* c0 = sacc[2 * ks];
            const float* c1 = sacc[2 * ks + 1];
            split2(c0[0], c0[1], ph[ks][0], pl[ks][0]);
            split2(c0[2], c0[3], ph[ks][1], pl[ks][1]);
            split2(c1[0], c1[1], ph[ks][2], pl[ks][2]);
            split2(c1[2], c1[3], ph[ks][3], pl[ks][3]);
        }

        // ---- O += P V ----
#pragma unroll
        for (int ks = 0; ks < 4; ks++) {
            uint32_t vbh[8][2], vbl[8][2];
#pragma unroll
            for (int pq = 0; pq < 4; pq++) {
                uint32_t off = bufOff + (uint32_t)(((ks * 16 + v_row) * FLDV) + pq * 16 + v_col) * 2;
                uint32_t t[4];
                ldsm_x4_t(t, sVh + off);
                vbh[2 * pq][0] = t[0]; vbh[2 * pq][1] = t[1];
                vbh[2 * pq + 1][0] = t[2]; vbh[2 * pq + 1][1] = t[3];
                ldsm_x4_t(t, sVl + off);
                vbl[2 * pq][0] = t[0]; vbl[2 * pq][1] = t[1];
                vbl[2 * pq + 1][0] = t[2]; vbl[2 * pq + 1][1] = t[3];
            }
#pragma unroll
            for (int dn = 0; dn < 8; dn++) {
                mma16816(o[dn], ph[ks], vbh[dn]);
                mma16816(o[dn], pl[ks], vbh[dn]);
                mma16816(o[dn], ph[ks], vbl[dn]);
            }
        }

        // ---- store prefetched tile into the other buffer ----
        if (hasNext) {
            const int eo = (p ^ 1) * (64 * FLDV) + lrow * FLDV + lcol;
            *(uint4*)(Kh + eo) = kh2[0]; *(uint4*)(Kh + eo + 8) = kh2[1];
            *(uint4*)(Kl + eo) = kl2[0]; *(uint4*)(Kl + eo + 8) = kl2[1];
            *(uint4*)(Vh + eo) = vh2[0]; *(uint4*)(Vh + eo + 8) = vh2[1];
            *(uint4*)(Vl + eo) = vl2[0]; *(uint4*)(Vl + eo + 8) = vl2[1];
        }
        __syncthreads();
        p ^= 1;
    }

    // ---- finalize: write ctx as bf16 hi/lo [B,S,H] ----
    float inv0 = 1.0f / lrun[0];
    float inv1 = 1.0f / lrun[1];
#pragma unroll
    for (int dn = 0; dn < 8; dn++) {
        int d = h * HD_ + dn * 8 + t2;
        int m0g = q0 + warp * 16 + g;
        size_t off0 = ((size_t)b * S_ + m0g) * H_ + d;
        size_t off1 = ((size_t)b * S_ + m0g + 8) * H_ + d;
        uint32_t hi, lo;
        split2(o[dn][0] * inv0, o[dn][1] * inv0, hi, lo);
        *(uint32_t*)&Ch[off0] = hi;
        *(uint32_t*)&Cl[off0] = lo;
        split2(o[dn][2] * inv1, o[dn][3] * inv1, hi, lo);
        *(uint32_t*)&Ch[off1] = hi;
        *(uint32_t*)&Cl[off1] = lo;
    }
}

// ---------------- layernorm (one block per row) --------------------------
__global__ __launch_bounds__(256) void layernorm_k(
    const float* __restrict__ hin, const float* __restrict__ gamma,
    const float* __restrict__ beta, float* __restrict__ out)
{
    const int row = blockIdx.x;
    const int t = threadIdx.x;
    const float* hp = hin + (size_t)row * H_;
    float* op = out + (size_t)row * H_;

    float4 x4 = ((const float4*)hp)[t];
    float sum = x4.x + x4.y + x4.z + x4.w;
    float sq  = x4.x * x4.x + x4.y * x4.y + x4.z * x4.z + x4.w * x4.w;

#pragma unroll
    for (int off = 16; off > 0; off >>= 1) {
        sum += __shfl_xor_sync(0xFFFFFFFFu, sum, off);
        sq  += __shfl_xor_sync(0xFFFFFFFFu, sq,  off);
    }
    __shared__ float ssum[8], ssq[8];
    const int wid = t >> 5, lid = t & 31;
    if (lid == 0) { ssum[wid] = sum; ssq[wid] = sq; }
    __syncthreads();
    if (wid == 0) {
        float a = (lid < 8) ? ssum[lid] : 0.f;
        float b = (lid < 8) ? ssq[lid]  : 0.f;
#pragma unroll
        for (int off = 4; off > 0; off >>= 1) {
            a += __shfl_xor_sync(0xFFFFFFFFu, a, off);
            b += __shfl_xor_sync(0xFFFFFFFFu, b, off);
        }
        if (lid == 0) { ssum[0] = a; ssq[0] = b; }
    }
    __syncthreads();
    const float mean = ssum[0] * (1.0f / H_);
    const float var  = ssq[0] * (1.0f / H_) - mean * mean;
    const float rstd = rsqrtf(var + 1e-12f);

    float4 g4 = ((const float4*)gamma)[t];
    float4 b4 = ((const float4*)beta)[t];
    float4 o4;
    o4.x = g4.x * (x4.x - mean) * rstd + b4.x;
    o4.y = g4.y * (x4.y - mean) * rstd + b4.y;
    o4.z = g4.z * (x4.z - mean) * rstd + b4.z;
    o4.w = g4.w * (x4.w - mean) * rstd + b4.w;
    ((float4*)op)[t] = o4;
}

// ---------------- launch ----------------
extern "C" void kernel_launch(void* const* d_in, const int* in_sizes, int n_in,
                              void* d_out, int out_size)
{
    const float* x     = (const float*)d_in[0];
    const float* wq    = (const float*)d_in[1];
    const float* bq    = (const float*)d_in[2];
    const float* wk    = (const float*)d_in[3];
    const float* bk    = (const float*)d_in[4];
    const float* wv    = (const float*)d_in[5];
    const float* bv    = (const float*)d_in[6];
    const float* wo    = (const float*)d_in[7];
    const float* bo    = (const float*)d_in[8];
    const float* gamma = (const float*)d_in[9];
    const float* beta  = (const float*)d_in[10];

    __nv_bfloat16 *xh, *xl, *wqh, *wql, *wkh, *wkl, *wvh, *wvl, *woh, *wol;
    __nv_bfloat16 *qh, *ql, *kh, *kl, *vh, *vl, *ch, *cl;
    float *hbuf;
    cudaGetSymbolAddress((void**)&xh,  g_xh);  cudaGetSymbolAddress((void**)&xl,  g_xl);
    cudaGetSymbolAddress((void**)&wqh, g_wqh); cudaGetSymbolAddress((void**)&wql, g_wql);
    cudaGetSymbolAddress((void**)&wkh, g_wkh); cudaGetSymbolAddress((void**)&wkl, g_wkl);
    cudaGetSymbolAddress((void**)&wvh, g_wvh); cudaGetSymbolAddress((void**)&wvl, g_wvl);
    cudaGetSymbolAddress((void**)&woh, g_woh); cudaGetSymbolAddress((void**)&wol, g_wol);
    cudaGetSymbolAddress((void**)&qh,  g_qh);  cudaGetSymbolAddress((void**)&ql,  g_ql);
    cudaGetSymbolAddress((void**)&kh,  g_kh);  cudaGetSymbolAddress((void**)&kl,  g_kl);
    cudaGetSymbolAddress((void**)&vh,  g_vh);  cudaGetSymbolAddress((void**)&vl,  g_vl);
    cudaGetSymbolAddress((void**)&ch,  g_ch);  cudaGetSymbolAddress((void**)&cl,  g_cl);
    cudaGetSymbolAddress((void**)&hbuf, g_h);

    cudaFuncSetAttribute(gemm_pre,
                         cudaFuncAttributeMaxDynamicSharedMemorySize, GEMM_SMEM);
    cudaFuncSetAttribute(flash_mma,
                         cudaFuncAttributeMaxDynamicSharedMemorySize, FLASH_SMEM);

    // ---- prep: pre-split x and weights into bf16 hi/lo ----
    {
        const int XN4 = MTOT * H_ / 4;    // 2,097,152
        const int WN4 = H_ * H_ / 4;      // 262,144
        split_pre<<<(XN4 + 255) / 256, 256>>>((const float4*)x,  (uint2*)xh,  (uint2*)xl,  XN4);
        split_pre<<<(WN4 + 255) / 256, 256>>>((const float4*)wq, (uint2*)wqh, (uint2*)wql, WN4);
        split_pre<<<(WN4 + 255) / 256, 256>>>((const float4*)wk, (uint2*)wkh, (uint2*)wkl, WN4);
        split_pre<<<(WN4 + 255) / 256, 256>>>((const float4*)wv, (uint2*)wvh, (uint2*)wvl, WN4);
        split_pre<<<(WN4 + 255) / 256, 256>>>((const float4*)wo, (uint2*)woh, (uint2*)wol, WN4);
    }

    // ---- fused QKV projections (z selects weights; q scaled by 1/8) ----
    gemm_pre<<<dim3(H_ / BN, MTOT / BM, 3), 256, GEMM_SMEM>>>(
        xh, xl, wqh, wql, wkh, wkl, wvh, wvl, bq, bk, bv,
        qh, ql, kh, kl, vh, vl, nullptr, nullptr, 1);

    // ---- flash attention ----
    flash_mma<<<dim3(S_ / 128, NH_, B_), 256, FLASH_SMEM>>>(
        qh, ql, kh, kl, vh, vl, ch, cl);

    // ---- output projection + residual (fp32 out) ----
    gemm_pre<<<dim3(H_ / BN, MTOT / BM, 1), 256, GEMM_SMEM>>>(
        ch, cl, woh, wol, woh, wol, woh, wol, bo, bo, bo,
        nullptr, nullptr, nullptr, nullptr, nullptr, nullptr, hbuf, x, 0);

    layernorm_k<<<MTOT, 256>>>(hbuf, gamma, beta, (float*)d_out);
}

// round 13
// speedup vs baseline: 1.5374x; 1.2659x over previous
#include <cuda_runtime.h>
#include <cuda_fp16.h>
#include <math.h>
#include <stdint.h>

#define B_   4
#define S_   2048
#define H_   1024
#define NH_  16
#define HD_  64
#define MTOT (B_ * S_)   // 8192
#define HEADN ((size_t)B_ * NH_ * S_ * HD_)

// ---------------- scratch (no allocs allowed) ----------------
__device__ __half g_xh[(size_t)MTOT * H_];                    // A hi only
__device__ __half g_wqh[(size_t)H_ * H_], g_wql[(size_t)H_ * H_];
__device__ __half g_wkh[(size_t)H_ * H_], g_wkl[(size_t)H_ * H_];
__device__ __half g_wvh[(size_t)H_ * H_], g_wvl[(size_t)H_ * H_];
__device__ __half g_woh[(size_t)H_ * H_], g_wol[(size_t)H_ * H_];
__device__ __half g_qh[HEADN];                                // hi only (A op)
__device__ __half g_kh[HEADN], g_kl[HEADN];                   // B op: hi+lo
__device__ __half g_vh[HEADN], g_vl[HEADN];                   // B op: hi+lo
__device__ __half g_ch[(size_t)MTOT * H_];                    // ctx hi only
__device__ float g_h[(size_t)MTOT * H_];                      // pre-LN fp32

// ---------------- common PTX helpers ----------------
__device__ __forceinline__ void mma16816h(float* c, const uint32_t* a, const uint32_t* b) {
    asm volatile(
        "mma.sync.aligned.m16n8k16.row.col.f32.f16.f16.f32 "
        "{%0,%1,%2,%3}, {%4,%5,%6,%7}, {%8,%9}, {%0,%1,%2,%3};\n"
        : "+f"(c[0]), "+f"(c[1]), "+f"(c[2]), "+f"(c[3])
        : "r"(a[0]), "r"(a[1]), "r"(a[2]), "r"(a[3]), "r"(b[0]), "r"(b[1]));
}
__device__ __forceinline__ void ldsm_x4(uint32_t* r, uint32_t addr) {
    asm volatile(
        "ldmatrix.sync.aligned.m8n8.x4.shared.b16 {%0,%1,%2,%3}, [%4];\n"
        : "=r"(r[0]), "=r"(r[1]), "=r"(r[2]), "=r"(r[3]) : "r"(addr));
}
__device__ __forceinline__ void ldsm_x4_t(uint32_t* r, uint32_t addr) {
    asm volatile(
        "ldmatrix.sync.aligned.m8n8.x4.trans.shared.b16 {%0,%1,%2,%3}, [%4];\n"
        : "=r"(r[0]), "=r"(r[1]), "=r"(r[2]), "=r"(r[3]) : "r"(addr));
}
// split two floats -> packed fp16x2 hi and lo
__device__ __forceinline__ void split2h(float x, float y, uint32_t& hi, uint32_t& lo) {
    __half hx = __float2half_rn(x), hy = __float2half_rn(y);
    __half lx = __float2half_rn(x - __half2float(hx));
    __half ly = __float2half_rn(y - __half2float(hy));
    __half2 h2 = __halves2half2(hx, hy);
    __half2 l2 = __halves2half2(lx, ly);
    hi = *(uint32_t*)&h2;
    lo = *(uint32_t*)&l2;
}
__device__ __forceinline__ uint32_t pack2h(float x, float y) {
    __half2 h2 = __floats2half2_rn(x, y);
    return *(uint32_t*)&h2;
}

// ---------------- prep kernels ----------------
__global__ __launch_bounds__(256) void split_hl(
    const float4* __restrict__ src, uint2* __restrict__ dh,
    uint2* __restrict__ dl, int n4)
{
    int i = blockIdx.x * blockDim.x + threadIdx.x;
    if (i >= n4) return;
    float4 f = src[i];
    uint32_t h0, l0, h1, l1;
    split2h(f.x, f.y, h0, l0);
    split2h(f.z, f.w, h1, l1);
    dh[i] = make_uint2(h0, h1);
    dl[i] = make_uint2(l0, l1);
}
__global__ __launch_bounds__(256) void split_hi_only(
    const float4* __restrict__ src, uint2* __restrict__ dh, int n4)
{
    int i = blockIdx.x * blockDim.x + threadIdx.x;
    if (i >= n4) return;
    float4 f = src[i];
    dh[i] = make_uint2(pack2h(f.x, f.y), pack2h(f.z, f.w));
}

// ============================================================
//  fp16x2 tensor-core GEMM: C = A_hi * (W_hi + W_lo)^T + bias
//  CTA 128x128, BK=32, double-buffered dynamic smem.
// ============================================================
#define BM 128
#define BN 128
#define BK 32
#define LDS_PAD 8
#define LDK (BK + LDS_PAD)      // 40 halves = 80 B row stride
#define G_ARR (2 * BM * LDK * 2)          // 20480 B per array (2 buffers)
#define GEMM_SMEM (3 * G_ARR)             // 61440 B  (A_h, B_h, B_l)

__global__ __launch_bounds__(256) void gemm_pre(
    const __half* __restrict__ Ah_,
    const __half* __restrict__ Wh0, const __half* __restrict__ Wl0,
    const __half* __restrict__ Wh1, const __half* __restrict__ Wl1,
    const __half* __restrict__ Wh2, const __half* __restrict__ Wl2,
    const float* __restrict__ bias0, const float* __restrict__ bias1, const float* __restrict__ bias2,
    __half* __restrict__ Oq,                                     // z==0: hi only
    __half* __restrict__ Okh, __half* __restrict__ Okl,          // z==1
    __half* __restrict__ Ovh, __half* __restrict__ Ovl,          // z==2
    float* __restrict__ Cf, const float* __restrict__ resid, int qkv_layout)
{
    extern __shared__ char smem[];
    const int K = H_;
    const int z = blockIdx.z;
    const __half* Wh = (z == 0) ? Wh0 : (z == 1) ? Wh1 : Wh2;
    const __half* Wl = (z == 0) ? Wl0 : (z == 1) ? Wl1 : Wl2;
    const float* bias = (z == 0) ? bias0 : (z == 1) ? bias1 : bias2;
    const float scale = (qkv_layout && z == 0) ? 0.125f : 1.0f;

    __half* sA_h = (__half*)(smem);
    __half* sB_h = (__half*)(smem + G_ARR);
    __half* sB_l = (__half*)(smem + 2 * G_ARR);

    const int tid  = threadIdx.x;
    const int warp = tid >> 5;
    const int lane = tid & 31;
    const int rowBase = blockIdx.y * BM;
    const int colBase = blockIdx.x * BN;

    const int m0 = (warp >> 1) * 32;
    const int n0 = (warp & 1) * 64;

    const int lrow = tid >> 1;
    const int lcol = (tid & 1) * 16;
    const __half* Agh = Ah_ + (size_t)(rowBase + lrow) * K + lcol;
    const __half* Wgh = Wh + (size_t)(colBase + lrow) * K + lcol;
    const __half* Wgl = Wl + (size_t)(colBase + lrow) * K + lcol;

    const int a_row = m0 + ((lane >> 3) & 1) * 8 + (lane & 7);
    const int a_col = ((lane >> 4) & 1) * 8;
    const int b_row = n0 + ((lane >> 4) & 1) * 8 + (lane & 7);
    const int b_col = ((lane >> 3) & 1) * 8;

    const uint32_t bufStride = (uint32_t)(BM * LDK * 2);
    const uint32_t sAhU = (uint32_t)__cvta_generic_to_shared(sA_h);
    const uint32_t sBhU = (uint32_t)__cvta_generic_to_shared(sB_h);
    const uint32_t sBlU = (uint32_t)__cvta_generic_to_shared(sB_l);

    float acc[2][8][4];
#pragma unroll
    for (int i = 0; i < 2; i++)
#pragma unroll
        for (int j = 0; j < 8; j++)
#pragma unroll
            for (int r = 0; r < 4; r++) acc[i][j][r] = 0.f;

    uint4 rah[2], rbh[2], rbl[2];
    rah[0] = *(const uint4*)(Agh);     rah[1] = *(const uint4*)(Agh + 8);
    rbh[0] = *(const uint4*)(Wgh);     rbh[1] = *(const uint4*)(Wgh + 8);
    rbl[0] = *(const uint4*)(Wgl);     rbl[1] = *(const uint4*)(Wgl + 8);
    {
        const int eo = lrow * LDK + lcol;
        *(uint4*)(sA_h + eo) = rah[0]; *(uint4*)(sA_h + eo + 8) = rah[1];
        *(uint4*)(sB_h + eo) = rbh[0]; *(uint4*)(sB_h + eo + 8) = rbh[1];
        *(uint4*)(sB_l + eo) = rbl[0]; *(uint4*)(sB_l + eo + 8) = rbl[1];
    }
    __syncthreads();

    int p = 0;
    for (int kt = 0; kt < K; kt += BK) {
        const bool hasNext = (kt + BK < K);
        if (hasNext) {
            rah[0] = *(const uint4*)(Agh + kt + BK);  rah[1] = *(const uint4*)(Agh + kt + BK + 8);
            rbh[0] = *(const uint4*)(Wgh + kt + BK);  rbh[1] = *(const uint4*)(Wgh + kt + BK + 8);
            rbl[0] = *(const uint4*)(Wgl + kt + BK);  rbl[1] = *(const uint4*)(Wgl + kt + BK + 8);
        }

        const uint32_t bufOff = (uint32_t)p * bufStride;
#pragma unroll
        for (int ks = 0; ks < 2; ks++) {
            const int kb = ks * 16;
            uint32_t ah[2][4], bh[8][2], bl[8][2];
#pragma unroll
            for (int mi = 0; mi < 2; mi++) {
                uint32_t off = bufOff + (uint32_t)(((a_row + mi * 16) * LDK) + kb + a_col) * 2;
                ldsm_x4(ah[mi], sAhU + off);
            }
#pragma unroll
            for (int pq = 0; pq < 4; pq++) {
                uint32_t off = bufOff + (uint32_t)(((b_row + pq * 16) * LDK) + kb + b_col) * 2;
                uint32_t t[4];
                ldsm_x4(t, sBhU + off);
                bh[2 * pq][0] = t[0]; bh[2 * pq][1] = t[1];
                bh[2 * pq + 1][0] = t[2]; bh[2 * pq + 1][1] = t[3];
                ldsm_x4(t, sBlU + off);
                bl[2 * pq][0] = t[0]; bl[2 * pq][1] = t[1];
                bl[2 * pq + 1][0] = t[2]; bl[2 * pq + 1][1] = t[3];
            }
#pragma unroll
            for (int nj = 0; nj < 8; nj++)
#pragma unroll
                for (int mi = 0; mi < 2; mi++) {
                    mma16816h(acc[mi][nj], ah[mi], bh[nj]);
                    mma16816h(acc[mi][nj], ah[mi], bl[nj]);
                }
        }

        if (hasNext) {
            const int eo = (p ^ 1) * (BM * LDK) + lrow * LDK + lcol;
            *(uint4*)(sA_h + eo) = rah[0]; *(uint4*)(sA_h + eo + 8) = rah[1];
            *(uint4*)(sB_h + eo) = rbh[0]; *(uint4*)(sB_h + eo + 8) = rbh[1];
            *(uint4*)(sB_l + eo) = rbl[0]; *(uint4*)(sB_l + eo + 8) = rbl[1];
        }
        __syncthreads();
        p ^= 1;
    }

    const int g  = lane >> 2;
    const int t2 = (lane & 3) * 2;
#pragma unroll
    for (int mi = 0; mi < 2; mi++) {
#pragma unroll
        for (int nj = 0; nj < 8; nj++) {
            int n = colBase + n0 + nj * 8 + t2;
            float bia0 = bias[n], bia1 = bias[n + 1];
#pragma unroll
            for (int rr = 0; rr < 2; rr++) {
                int m = rowBase + m0 + mi * 16 + g + rr * 8;
                float v0 = acc[mi][nj][rr * 2 + 0] + bia0;
                float v1 = acc[mi][nj][rr * 2 + 1] + bia1;
                if (qkv_layout) {
                    int bb = m >> 11, ss = m & (S_ - 1);
                    int hh = n >> 6, dd = n & (HD_ - 1);
                    size_t off = ((((size_t)bb * NH_) + hh) * S_ + ss) * HD_ + dd;
                    if (z == 0) {
                        *(uint32_t*)&Oq[off] = pack2h(v0 * scale, v1 * scale);
                    } else {
                        uint32_t hi, lo;
                        split2h(v0, v1, hi, lo);
                        if (z == 1) {
                            *(uint32_t*)&Okh[off] = hi;
                            *(uint32_t*)&Okl[off] = lo;
                        } else {
                            *(uint32_t*)&Ovh[off] = hi;
                            *(uint32_t*)&Ovl[off] = lo;
                        }
                    }
                } else {
                    const float2 rs = *(const float2*)&resid[(size_t)m * H_ + n];
                    *(float2*)&Cf[(size_t)m * H_ + n] = make_float2(v0 + rs.x, v1 + rs.y);
                }
            }
        }
    }
}

// ============================================================
//  fp16x2 flash attention, 128 q x 64 kv tiles, 256 threads,
//  double-buffered dynamic smem, reg prefetch.
// ============================================================
#define FLDV 72
#define F_ARR (2 * 64 * FLDV * 2)
#define FLASH_SMEM (4 * F_ARR)

__global__ __launch_bounds__(256) void flash_mma(
    const __half* __restrict__ Qh, const __half* __restrict__ Kgh,
    const __half* __restrict__ Kgl, const __half* __restrict__ Vgh,
    const __half* __restrict__ Vgl, __half* __restrict__ Ch)
{
    extern __shared__ char smem[];
    __half* Kh = (__half*)(smem);
    __half* Kl = (__half*)(smem + F_ARR);
    __half* Vh = (__half*)(smem + 2 * F_ARR);
    __half* Vl = (__half*)(smem + 3 * F_ARR);

    const int b = blockIdx.z;
    const int h = blockIdx.y;
    const int tid  = threadIdx.x;
    const int warp = tid >> 5;
    const int lane = tid & 31;
    const int q0 = blockIdx.x * 128;

    const size_t headBase = (((size_t)b * NH_ + h) * S_) * HD_;

    const int lrow = tid >> 2;
    const int lcol = (tid & 3) * 16;

    const int b_row = ((lane >> 4) & 1) * 8 + (lane & 7);
    const int b_col = ((lane >> 3) & 1) * 8;
    const int v_row = ((lane >> 3) & 1) * 8 + (lane & 7);
    const int v_col = ((lane >> 4) & 1) * 8;

    const uint32_t bufStride = (uint32_t)(64 * FLDV * 2);
    const uint32_t sKh = (uint32_t)__cvta_generic_to_shared(Kh);
    const uint32_t sKl = (uint32_t)__cvta_generic_to_shared(Kl);
    const uint32_t sVh = (uint32_t)__cvta_generic_to_shared(Vh);
    const uint32_t sVl = (uint32_t)__cvta_generic_to_shared(Vl);

    const int g  = lane >> 2;
    const int t2 = (lane & 3) * 2;

    // ---- Q fragments (hi only) straight from gmem ----
    uint32_t qh[4][4];
    {
        const __half* qh0 = Qh + headBase + (size_t)(q0 + warp * 16 + g) * HD_;
        const __half* qh1 = qh0 + 8 * HD_;
#pragma unroll
        for (int ks = 0; ks < 4; ks++) {
            int c = ks * 16 + t2;
            qh[ks][0] = *(const uint32_t*)(qh0 + c);
            qh[ks][1] = *(const uint32_t*)(qh1 + c);
            qh[ks][2] = *(const uint32_t*)(qh0 + c + 8);
            qh[ks][3] = *(const uint32_t*)(qh1 + c + 8);
        }
    }

    float o[8][4];
#pragma unroll
    for (int dn = 0; dn < 8; dn++)
#pragma unroll
        for (int e = 0; e < 4; e++) o[dn][e] = 0.f;
    float mrun[2] = {-1e30f, -1e30f};
    float lrun[2] = {0.f, 0.f};

    // ---- prologue: tile 0 -> regs -> buffer 0 ----
    uint4 kh2[2], kl2[2], vh2[2], vl2[2];
    {
        const __half* kgh = Kgh + headBase + (size_t)lrow * HD_ + lcol;
        const __half* kgl = Kgl + headBase + (size_t)lrow * HD_ + lcol;
        const __half* vgh = Vgh + headBase + (size_t)lrow * HD_ + lcol;
        const __half* vgl = Vgl + headBase + (size_t)lrow * HD_ + lcol;
        kh2[0] = *(const uint4*)(kgh); kh2[1] = *(const uint4*)(kgh + 8);
        kl2[0] = *(const uint4*)(kgl); kl2[1] = *(const uint4*)(kgl + 8);
        vh2[0] = *(const uint4*)(vgh); vh2[1] = *(const uint4*)(vgh + 8);
        vl2[0] = *(const uint4*)(vgl); vl2[1] = *(const uint4*)(vgl + 8);
        const int eo = lrow * FLDV + lcol;
        *(uint4*)(Kh + eo) = kh2[0]; *(uint4*)(Kh + eo + 8) = kh2[1];
        *(uint4*)(Kl + eo) = kl2[0]; *(uint4*)(Kl + eo + 8) = kl2[1];
        *(uint4*)(Vh + eo) = vh2[0]; *(uint4*)(Vh + eo + 8) = vh2[1];
        *(uint4*)(Vl + eo) = vl2[0]; *(uint4*)(Vl + eo + 8) = vl2[1];
    }
    __syncthreads();

    int p = 0;
    for (int j0 = 0; j0 < S_; j0 += 64) {
        const bool hasNext = (j0 + 64 < S_);
        if (hasNext) {
            const __half* kgh = Kgh + headBase + (size_t)(j0 + 64 + lrow) * HD_ + lcol;
            const __half* kgl = Kgl + headBase + (size_t)(j0 + 64 + lrow) * HD_ + lcol;
            const __half* vgh = Vgh + headBase + (size_t)(j0 + 64 + lrow) * HD_ + lcol;
            const __half* vgl = Vgl + headBase + (size_t)(j0 + 64 + lrow) * HD_ + lcol;
            kh2[0] = *(const uint4*)(kgh); kh2[1] = *(const uint4*)(kgh + 8);
            kl2[0] = *(const uint4*)(kgl); kl2[1] = *(const uint4*)(kgl + 8);
            vh2[0] = *(const uint4*)(vgh); vh2[1] = *(const uint4*)(vgh + 8);
            vl2[0] = *(const uint4*)(vgl); vl2[1] = *(const uint4*)(vgl + 8);
        }

        const uint32_t bufOff = (uint32_t)p * bufStride;

        // ---- S = Q_hi (K_hi + K_lo)^T ----
        float sacc[8][4];
#pragma unroll
        for (int nj = 0; nj < 8; nj++)
#pragma unroll
            for (int e = 0; e < 4; e++) sacc[nj][e] = 0.f;

#pragma unroll
        for (int ks = 0; ks < 4; ks++) {
            uint32_t bh[8][2], bl[8][2];
#pragma unroll
            for (int pq = 0; pq < 4; pq++) {
                uint32_t off = bufOff + (uint32_t)(((pq * 16 + b_row) * FLDV) + ks * 16 + b_col) * 2;
                uint32_t t[4];
                ldsm_x4(t, sKh + off);
                bh[2 * pq][0] = t[0]; bh[2 * pq][1] = t[1];
                bh[2 * pq + 1][0] = t[2]; bh[2 * pq + 1][1] = t[3];
                ldsm_x4(t, sKl + off);
                bl[2 * pq][0] = t[0]; bl[2 * pq][1] = t[1];
                bl[2 * pq + 1][0] = t[2]; bl[2 * pq + 1][1] = t[3];
            }
#pragma unroll
            for (int nj = 0; nj < 8; nj++) {
                mma16816h(sacc[nj], qh[ks], bh[nj]);
                mma16816h(sacc[nj], qh[ks], bl[nj]);
            }
        }

        // ---- online softmax ----
        float mloc[2] = {-1e30f, -1e30f};
#pragma unroll
        for (int nj = 0; nj < 8; nj++) {
            mloc[0] = fmaxf(mloc[0], fmaxf(sacc[nj][0], sacc[nj][1]));
            mloc[1] = fmaxf(mloc[1], fmaxf(sacc[nj][2], sacc[nj][3]));
        }
#pragma unroll
        for (int r = 0; r < 2; r++) {
            mloc[r] = fmaxf(mloc[r], __shfl_xor_sync(0xFFFFFFFFu, mloc[r], 1));
            mloc[r] = fmaxf(mloc[r], __shfl_xor_sync(0xFFFFFFFFu, mloc[r], 2));
        }
        float corr[2];
#pragma unroll
        for (int r = 0; r < 2; r++) {
            float mnew = fmaxf(mrun[r], mloc[r]);
            corr[r] = __expf(mrun[r] - mnew);
            mrun[r] = mnew;
        }
        float psum[2] = {0.f, 0.f};
#pragma unroll
        for (int nj = 0; nj < 8; nj++) {
            float p0 = __expf(sacc[nj][0] - mrun[0]);
            float p1 = __expf(sacc[nj][1] - mrun[0]);
            float p2 = __expf(sacc[nj][2] - mrun[1]);
            float p3 = __expf(sacc[nj][3] - mrun[1]);
            sacc[nj][0] = p0; sacc[nj][1] = p1;
            sacc[nj][2] = p2; sacc[nj][3] = p3;
            psum[0] += p0 + p1;
            psum[1] += p2 + p3;
        }
#pragma unroll
        for (int r = 0; r < 2; r++) {
            psum[r] += __shfl_xor_sync(0xFFFFFFFFu, psum[r], 1);
            psum[r] += __shfl_xor_sync(0xFFFFFFFFu, psum[r], 2);
            lrun[r] = lrun[r] * corr[r] + psum[r];
        }
#pragma unroll
        for (int dn = 0; dn < 8; dn++) {
            o[dn][0] *= corr[0]; o[dn][1] *= corr[0];
            o[dn][2] *= corr[1]; o[dn][3] *= corr[1];
        }

        // ---- repack P (hi only) -> A-frags ----
        uint32_t ph[4][4];
#pragma unroll
        for (int ks = 0; ks < 4; ks++) {
            const float* c0 = sacc[2 * ks];
            const float* c1 = sacc[2 * ks + 1];
            ph[ks][0] = pack2h(c0[0], c0[1]);
            ph[ks][1] = pack2h(c0[2], c0[3]);
            ph[ks][2] = pack2h(c1[0], c1[1]);
            ph[ks][3] = pack2h(c1[2], c1[3]);
        }

        // ---- O += P_hi (V_hi + V_lo) ----
#pragma unroll
        for (int ks = 0; ks < 4; ks++) {
            uint32_t vbh[8][2], vbl[8][2];
#pragma unroll
            for (int pq = 0; pq < 4; pq++) {
                uint32_t off = bufOff + (uint32_t)(((ks * 16 + v_row) * FLDV) + pq * 16 + v_col) * 2;
                uint32_t t[4];
                ldsm_x4_t(t, sVh + off);
                vbh[2 * pq][0] = t[0]; vbh[2 * pq][1] = t[1];
                vbh[2 * pq + 1][0] = t[2]; vbh[2 * pq + 1][1] = t[3];
                ldsm_x4_t(t, sVl + off);
                vbl[2 * pq][0] = t[0]; vbl[2 * pq][1] = t[1];
                vbl[2 * pq + 1][0] = t[2]; vbl[2 * pq + 1][1] = t[3];
            }
#pragma unroll
            for (int dn = 0; dn < 8; dn++) {
                mma16816h(o[dn], ph[ks], vbh[dn]);
                mma16816h(o[dn], ph[ks], vbl[dn]);
            }
        }

        // ---- store prefetched tile into the other buffer ----
        if (hasNext) {
            const int eo = (p ^ 1) * (64 * FLDV) + lrow * FLDV + lcol;
            *(uint4*)(Kh + eo) = kh2[0]; *(uint4*)(Kh + eo + 8) = kh2[1];
            *(uint4*)(Kl + eo) = kl2[0]; *(uint4*)(Kl + eo + 8) = kl2[1];
            *(uint4*)(Vh + eo) = vh2[0]; *(uint4*)(Vh + eo + 8) = vh2[1];
            *(uint4*)(Vl + eo) = vl2[0]; *(uint4*)(Vl + eo + 8) = vl2[1];
        }
        __syncthreads();
        p ^= 1;
    }

    // ---- finalize: write ctx as fp16 hi [B,S,H] ----
    float inv0 = 1.0f / lrun[0];
    float inv1 = 1.0f / lrun[1];
#pragma unroll
    for (int dn = 0; dn < 8; dn++) {
        int d = h * HD_ + dn * 8 + t2;
        int m0g = q0 + warp * 16 + g;
        size_t off0 = ((size_t)b * S_ + m0g) * H_ + d;
        size_t off1 = ((size_t)b * S_ + m0g + 8) * H_ + d;
        *(uint32_t*)&Ch[off0] = pack2h(o[dn][0] * inv0, o[dn][1] * inv0);
        *(uint32_t*)&Ch[off1] = pack2h(o[dn][2] * inv1, o[dn][3] * inv1);
    }
}

// ---------------- layernorm (one block per row) --------------------------
__global__ __launch_bounds__(256) void layernorm_k(
    const float* __restrict__ hin, const float* __restrict__ gamma,
    const float* __restrict__ beta, float* __restrict__ out)
{
    const int row = blockIdx.x;
    const int t = threadIdx.x;
    const float* hp = hin + (size_t)row * H_;
    float* op = out + (size_t)row * H_;

    float4 x4 = ((const float4*)hp)[t];
    float sum = x4.x + x4.y + x4.z + x4.w;
    float sq  = x4.x * x4.x + x4.y * x4.y + x4.z * x4.z + x4.w * x4.w;

#pragma unroll
    for (int off = 16; off > 0; off >>= 1) {
        sum += __shfl_xor_sync(0xFFFFFFFFu, sum, off);
        sq  += __shfl_xor_sync(0xFFFFFFFFu, sq,  off);
    }
    __shared__ float ssum[8], ssq[8];
    const int wid = t >> 5, lid = t & 31;
    if (lid == 0) { ssum[wid] = sum; ssq[wid] = sq; }
    __syncthreads();
    if (wid == 0) {
        float a = (lid < 8) ? ssum[lid] : 0.f;
        float b = (lid < 8) ? ssq[lid]  : 0.f;
#pragma unroll
        for (int off = 4; off > 0; off >>= 1) {
            a += __shfl_xor_sync(0xFFFFFFFFu, a, off);
            b += __shfl_xor_sync(0xFFFFFFFFu, b, off);
        }
        if (lid == 0) { ssum[0] = a; ssq[0] = b; }
    }
    __syncthreads();
    const float mean = ssum[0] * (1.0f / H_);
    const float var  = ssq[0] * (1.0f / H_) - mean * mean;
    const float rstd = rsqrtf(var + 1e-12f);

    float4 g4 = ((const float4*)gamma)[t];
    float4 b4 = ((const float4*)beta)[t];
    float4 o4;
    o4.x = g4.x * (x4.x - mean) * rstd + b4.x;
    o4.y = g4.y * (x4.y - mean) * rstd + b4.y;
    o4.z = g4.z * (x4.z - mean) * rstd + b4.z;
    o4.w = g4.w * (x4.w - mean) * rstd + b4.w;
    ((float4*)op)[t] = o4;
}

// ---------------- launch ----------------
extern "C" void kernel_launch(void* const* d_in, const int* in_sizes, int n_in,
                              void* d_out, int out_size)
{
    const float* x     = (const float*)d_in[0];
    const float* wq    = (const float*)d_in[1];
    const float* bq    = (const float*)d_in[2];
    const float* wk    = (const float*)d_in[3];
    const float* bk    = (const float*)d_in[4];
    const float* wv    = (const float*)d_in[5];
    const float* bv    = (const float*)d_in[6];
    const float* wo    = (const float*)d_in[7];
    const float* bo    = (const float*)d_in[8];
    const float* gamma = (const float*)d_in[9];
    const float* beta  = (const float*)d_in[10];

    __half *xh, *wqh, *wql, *wkh, *wkl, *wvh, *wvl, *woh, *wol;
    __half *qh, *kh, *kl, *vh, *vl, *ch;
    float *hbuf;
    cudaGetSymbolAddress((void**)&xh,  g_xh);
    cudaGetSymbolAddress((void**)&wqh, g_wqh); cudaGetSymbolAddress((void**)&wql, g_wql);
    cudaGetSymbolAddress((void**)&wkh, g_wkh); cudaGetSymbolAddress((void**)&wkl, g_wkl);
    cudaGetSymbolAddress((void**)&wvh, g_wvh); cudaGetSymbolAddress((void**)&wvl, g_wvl);
    cudaGetSymbolAddress((void**)&woh, g_woh); cudaGetSymbolAddress((void**)&wol, g_wol);
    cudaGetSymbolAddress((void**)&qh,  g_qh);
    cudaGetSymbolAddress((void**)&kh,  g_kh);  cudaGetSymbolAddress((void**)&kl,  g_kl);
    cudaGetSymbolAddress((void**)&vh,  g_vh);  cudaGetSymbolAddress((void**)&vl,  g_vl);
    cudaGetSymbolAddress((void**)&ch,  g_ch);
    cudaGetSymbolAddress((void**)&hbuf, g_h);

    cudaFuncSetAttribute(gemm_pre,
                         cudaFuncAttributeMaxDynamicSharedMemorySize, GEMM_SMEM);
    cudaFuncSetAttribute(flash_mma,
                         cudaFuncAttributeMaxDynamicSharedMemorySize, FLASH_SMEM);

    // ---- prep: x -> fp16 hi; weights -> fp16 hi/lo ----
    {
        const int XN4 = MTOT * H_ / 4;
        const int WN4 = H_ * H_ / 4;
        split_hi_only<<<(XN4 + 255) / 256, 256>>>((const float4*)x, (uint2*)xh, XN4);
        split_hl<<<(WN4 + 255) / 256, 256>>>((const float4*)wq, (uint2*)wqh, (uint2*)wql, WN4);
        split_hl<<<(WN4 + 255) / 256, 256>>>((const float4*)wk, (uint2*)wkh, (uint2*)wkl, WN4);
        split_hl<<<(WN4 + 255) / 256, 256>>>((const float4*)wv, (uint2*)wvh, (uint2*)wvl, WN4);
        split_hl<<<(WN4 + 255) / 256, 256>>>((const float4*)wo, (uint2*)woh, (uint2*)wol, WN4);
    }

    // ---- fused QKV projections (z selects weights; q scaled by 1/8) ----
    gemm_pre<<<dim3(H_ / BN, MTOT / BM, 3), 256, GEMM_SMEM>>>(
        xh, wqh, wql, wkh, wkl, wvh, wvl, bq, bk, bv,
        qh, kh, kl, vh, vl, nullptr, nullptr, 1);

    // ---- flash attention ----
    flash_mma<<<dim3(S_ / 128, NH_, B_), 256, FLASH_SMEM>>>(
        qh, kh, kl, vh, vl, ch);

    // ---- output projection + residual (fp32 out) ----
    gemm_pre<<<dim3(H_ / BN, MTOT / BM, 1), 256, GEMM_SMEM>>>(
        ch, woh, wol, woh, wol, woh, wol, bo, bo, bo,
        nullptr, nullptr, nullptr, nullptr, nullptr, hbuf, x, 0);

    layernorm_k<<<MTOT, 256>>>(hbuf, gamma, beta, (float*)d_out);
}

// round 14
// speedup vs baseline: 2.7032x; 1.7583x over previous
#include <cuda_runtime.h>
#include <cuda_fp16.h>
#include <math.h>
#include <stdint.h>

#define B_   4
#define S_   2048
#define H_   1024
#define NH_  16
#define HD_  64
#define MTOT (B_ * S_)   // 8192
#define HEADN ((size_t)B_ * NH_ * S_ * HD_)

// ---------------- scratch (no allocs allowed) ----------------
__device__ __half g_xh[(size_t)MTOT * H_];
__device__ __half g_wqh[(size_t)H_ * H_];
__device__ __half g_wkh[(size_t)H_ * H_];
__device__ __half g_wvh[(size_t)H_ * H_];
__device__ __half g_woh[(size_t)H_ * H_];
__device__ __half g_qh[HEADN];
__device__ __half g_kh[HEADN];
__device__ __half g_vh[HEADN];
__device__ __half g_ch[(size_t)MTOT * H_];
__device__ float g_h[(size_t)MTOT * H_];      // pre-LN fp32

// ---------------- common PTX helpers ----------------
__device__ __forceinline__ void mma16816h(float* c, const uint32_t* a, const uint32_t* b) {
    asm volatile(
        "mma.sync.aligned.m16n8k16.row.col.f32.f16.f16.f32 "
        "{%0,%1,%2,%3}, {%4,%5,%6,%7}, {%8,%9}, {%0,%1,%2,%3};\n"
        : "+f"(c[0]), "+f"(c[1]), "+f"(c[2]), "+f"(c[3])
        : "r"(a[0]), "r"(a[1]), "r"(a[2]), "r"(a[3]), "r"(b[0]), "r"(b[1]));
}
__device__ __forceinline__ void ldsm_x4(uint32_t* r, uint32_t addr) {
    asm volatile(
        "ldmatrix.sync.aligned.m8n8.x4.shared.b16 {%0,%1,%2,%3}, [%4];\n"
        : "=r"(r[0]), "=r"(r[1]), "=r"(r[2]), "=r"(r[3]) : "r"(addr));
}
__device__ __forceinline__ void ldsm_x4_t(uint32_t* r, uint32_t addr) {
    asm volatile(
        "ldmatrix.sync.aligned.m8n8.x4.trans.shared.b16 {%0,%1,%2,%3}, [%4];\n"
        : "=r"(r[0]), "=r"(r[1]), "=r"(r[2]), "=r"(r[3]) : "r"(addr));
}
__device__ __forceinline__ uint32_t pack2h(float x, float y) {
    __half2 h2 = __floats2half2_rn(x, y);
    return *(uint32_t*)&h2;
}

// ---------------- prep: fp32 -> fp16 ----------------
__global__ __launch_bounds__(256) void split_hi_only(
    const float4* __restrict__ src, uint2* __restrict__ dh, int n4)
{
    int i = blockIdx.x * blockDim.x + threadIdx.x;
    if (i >= n4) return;
    float4 f = src[i];
    dh[i] = make_uint2(pack2h(f.x, f.y), pack2h(f.z, f.w));
}

// ============================================================
//  fp16 tensor-core GEMM: C = A * W^T + bias
//  CTA 128x128, BK=32, double-buffered dynamic smem.
// ============================================================
#define BM 128
#define BN 128
#define BK 32
#define LDS_PAD 8
#define LDK (BK + LDS_PAD)      // 40 halves = 80 B row stride
#define G_ARR (2 * BM * LDK * 2)          // 20480 B per array (2 buffers)
#define GEMM_SMEM (2 * G_ARR)             // 40960 B  (A, B)

__global__ __launch_bounds__(256) void gemm_pre(
    const __half* __restrict__ Ah_,
    const __half* __restrict__ Wh0, const __half* __restrict__ Wh1, const __half* __restrict__ Wh2,
    const float* __restrict__ bias0, const float* __restrict__ bias1, const float* __restrict__ bias2,
    __half* __restrict__ Oq, __half* __restrict__ Ok, __half* __restrict__ Ov,
    float* __restrict__ Cf, const float* __restrict__ resid, int qkv_layout)
{
    extern __shared__ char smem[];
    const int K = H_;
    const int z = blockIdx.z;
    const __half* Wh = (z == 0) ? Wh0 : (z == 1) ? Wh1 : Wh2;
    const float* bias = (z == 0) ? bias0 : (z == 1) ? bias1 : bias2;
    __half* Oc = (z == 0) ? Oq : (z == 1) ? Ok : Ov;
    const float scale = (qkv_layout && z == 0) ? 0.125f : 1.0f;

    __half* sA = (__half*)(smem);
    __half* sB = (__half*)(smem + G_ARR);

    const int tid  = threadIdx.x;
    const int warp = tid >> 5;
    const int lane = tid & 31;
    const int rowBase = blockIdx.y * BM;
    const int colBase = blockIdx.x * BN;

    const int m0 = (warp >> 1) * 32;
    const int n0 = (warp & 1) * 64;

    const int lrow = tid >> 1;
    const int lcol = (tid & 1) * 16;
    const __half* Ag = Ah_ + (size_t)(rowBase + lrow) * K + lcol;
    const __half* Wg = Wh + (size_t)(colBase + lrow) * K + lcol;

    const int a_row = m0 + ((lane >> 3) & 1) * 8 + (lane & 7);
    const int a_col = ((lane >> 4) & 1) * 8;
    const int b_row = n0 + ((lane >> 4) & 1) * 8 + (lane & 7);
    const int b_col = ((lane >> 3) & 1) * 8;

    const uint32_t bufStride = (uint32_t)(BM * LDK * 2);
    const uint32_t sAU = (uint32_t)__cvta_generic_to_shared(sA);
    const uint32_t sBU = (uint32_t)__cvta_generic_to_shared(sB);

    float acc[2][8][4];
#pragma unroll
    for (int i = 0; i < 2; i++)
#pragma unroll
        for (int j = 0; j < 8; j++)
#pragma unroll
            for (int r = 0; r < 4; r++) acc[i][j][r] = 0.f;

    uint4 ra[2], rb[2];
    ra[0] = *(const uint4*)(Ag);     ra[1] = *(const uint4*)(Ag + 8);
    rb[0] = *(const uint4*)(Wg);     rb[1] = *(const uint4*)(Wg + 8);
    {
        const int eo = lrow * LDK + lcol;
        *(uint4*)(sA + eo) = ra[0]; *(uint4*)(sA + eo + 8) = ra[1];
        *(uint4*)(sB + eo) = rb[0]; *(uint4*)(sB + eo + 8) = rb[1];
    }
    __syncthreads();

    int p = 0;
    for (int kt = 0; kt < K; kt += BK) {
        const bool hasNext = (kt + BK < K);
        if (hasNext) {
            ra[0] = *(const uint4*)(Ag + kt + BK);  ra[1] = *(const uint4*)(Ag + kt + BK + 8);
            rb[0] = *(const uint4*)(Wg + kt + BK);  rb[1] = *(const uint4*)(Wg + kt + BK + 8);
        }

        const uint32_t bufOff = (uint32_t)p * bufStride;
#pragma unroll
        for (int ks = 0; ks < 2; ks++) {
            const int kb = ks * 16;
            uint32_t ah[2][4], bh[8][2];
#pragma unroll
            for (int mi = 0; mi < 2; mi++) {
                uint32_t off = bufOff + (uint32_t)(((a_row + mi * 16) * LDK) + kb + a_col) * 2;
                ldsm_x4(ah[mi], sAU + off);
            }
#pragma unroll
            for (int pq = 0; pq < 4; pq++) {
                uint32_t off = bufOff + (uint32_t)(((b_row + pq * 16) * LDK) + kb + b_col) * 2;
                uint32_t t[4];
                ldsm_x4(t, sBU + off);
                bh[2 * pq][0] = t[0]; bh[2 * pq][1] = t[1];
                bh[2 * pq + 1][0] = t[2]; bh[2 * pq + 1][1] = t[3];
            }
#pragma unroll
            for (int nj = 0; nj < 8; nj++)
#pragma unroll
                for (int mi = 0; mi < 2; mi++)
                    mma16816h(acc[mi][nj], ah[mi], bh[nj]);
        }

        if (hasNext) {
            const int eo = (p ^ 1) * (BM * LDK) + lrow * LDK + lcol;
            *(uint4*)(sA + eo) = ra[0]; *(uint4*)(sA + eo + 8) = ra[1];
            *(uint4*)(sB + eo) = rb[0]; *(uint4*)(sB + eo + 8) = rb[1];
        }
        __syncthreads();
        p ^= 1;
    }

    const int g  = lane >> 2;
    const int t2 = (lane & 3) * 2;
#pragma unroll
    for (int mi = 0; mi < 2; mi++) {
#pragma unroll
        for (int nj = 0; nj < 8; nj++) {
            int n = colBase + n0 + nj * 8 + t2;
            float bia0 = bias[n], bia1 = bias[n + 1];
#pragma unroll
            for (int rr = 0; rr < 2; rr++) {
                int m = rowBase + m0 + mi * 16 + g + rr * 8;
                float v0 = acc[mi][nj][rr * 2 + 0] + bia0;
                float v1 = acc[mi][nj][rr * 2 + 1] + bia1;
                if (qkv_layout) {
                    int bb = m >> 11, ss = m & (S_ - 1);
                    int hh = n >> 6, dd = n & (HD_ - 1);
                    size_t off = ((((size_t)bb * NH_) + hh) * S_ + ss) * HD_ + dd;
                    *(uint32_t*)&Oc[off] = pack2h(v0 * scale, v1 * scale);
                } else {
                    const float2 rs = *(const float2*)&resid[(size_t)m * H_ + n];
                    *(float2*)&Cf[(size_t)m * H_ + n] = make_float2(v0 + rs.x, v1 + rs.y);
                }
            }
        }
    }
}

// ============================================================
//  fp16 flash attention, 128 q x 64 kv tiles, 256 threads,
//  double-buffered dynamic smem, reg prefetch, 2 CTA/SM.
// ============================================================
#define FLDV 72
#define F_ARR (2 * 64 * FLDV * 2)          // 18432 B (both buffers)
#define FLASH_SMEM (2 * F_ARR)             // 36864 B (K, V)

__global__ __launch_bounds__(256, 2) void flash_mma(
    const __half* __restrict__ Qh, const __half* __restrict__ Kgh,
    const __half* __restrict__ Vgh, __half* __restrict__ Ch)
{
    extern __shared__ char smem[];
    __half* Kh = (__half*)(smem);
    __half* Vh = (__half*)(smem + F_ARR);

    const int b = blockIdx.z;
    const int h = blockIdx.y;
    const int tid  = threadIdx.x;
    const int warp = tid >> 5;
    const int lane = tid & 31;
    const int q0 = blockIdx.x * 128;

    const size_t headBase = (((size_t)b * NH_ + h) * S_) * HD_;

    const int lrow = tid >> 2;
    const int lcol = (tid & 3) * 16;

    const int b_row = ((lane >> 4) & 1) * 8 + (lane & 7);
    const int b_col = ((lane >> 3) & 1) * 8;
    const int v_row = ((lane >> 3) & 1) * 8 + (lane & 7);
    const int v_col = ((lane >> 4) & 1) * 8;

    const uint32_t bufStride = (uint32_t)(64 * FLDV * 2);
    const uint32_t sKh = (uint32_t)__cvta_generic_to_shared(Kh);
    const uint32_t sVh = (uint32_t)__cvta_generic_to_shared(Vh);

    const int g  = lane >> 2;
    const int t2 = (lane & 3) * 2;

    // ---- Q fragments straight from gmem (already scaled) ----
    uint32_t qh[4][4];
    {
        const __half* qh0 = Qh + headBase + (size_t)(q0 + warp * 16 + g) * HD_;
        const __half* qh1 = qh0 + 8 * HD_;
#pragma unroll
        for (int ks = 0; ks < 4; ks++) {
            int c = ks * 16 + t2;
            qh[ks][0] = *(const uint32_t*)(qh0 + c);
            qh[ks][1] = *(const uint32_t*)(qh1 + c);
            qh[ks][2] = *(const uint32_t*)(qh0 + c + 8);
            qh[ks][3] = *(const uint32_t*)(qh1 + c + 8);
        }
    }

    float o[8][4];
#pragma unroll
    for (int dn = 0; dn < 8; dn++)
#pragma unroll
        for (int e = 0; e < 4; e++) o[dn][e] = 0.f;
    float mrun[2] = {-1e30f, -1e30f};
    float lrun[2] = {0.f, 0.f};

    // ---- prologue: tile 0 -> regs -> buffer 0 ----
    uint4 kh2[2], vh2[2];
    {
        const __half* kg = Kgh + headBase + (size_t)lrow * HD_ + lcol;
        const __half* vg = Vgh + headBase + (size_t)lrow * HD_ + lcol;
        kh2[0] = *(const uint4*)(kg); kh2[1] = *(const uint4*)(kg + 8);
        vh2[0] = *(const uint4*)(vg); vh2[1] = *(const uint4*)(vg + 8);
        const int eo = lrow * FLDV + lcol;
        *(uint4*)(Kh + eo) = kh2[0]; *(uint4*)(Kh + eo + 8) = kh2[1];
        *(uint4*)(Vh + eo) = vh2[0]; *(uint4*)(Vh + eo + 8) = vh2[1];
    }
    __syncthreads();

    int p = 0;
    for (int j0 = 0; j0 < S_; j0 += 64) {
        const bool hasNext = (j0 + 64 < S_);
        if (hasNext) {
            const __half* kg = Kgh + headBase + (size_t)(j0 + 64 + lrow) * HD_ + lcol;
            const __half* vg = Vgh + headBase + (size_t)(j0 + 64 + lrow) * HD_ + lcol;
            kh2[0] = *(const uint4*)(kg); kh2[1] = *(const uint4*)(kg + 8);
            vh2[0] = *(const uint4*)(vg); vh2[1] = *(const uint4*)(vg + 8);
        }

        const uint32_t bufOff = (uint32_t)p * bufStride;

        // ---- S = Q K^T ----
        float sacc[8][4];
#pragma unroll
        for (int nj = 0; nj < 8; nj++)
#pragma unroll
            for (int e = 0; e < 4; e++) sacc[nj][e] = 0.f;

#pragma unroll
        for (int ks = 0; ks < 4; ks++) {
            uint32_t bh[8][2];
#pragma unroll
            for (int pq = 0; pq < 4; pq++) {
                uint32_t off = bufOff + (uint32_t)(((pq * 16 + b_row) * FLDV) + ks * 16 + b_col) * 2;
                uint32_t t[4];
                ldsm_x4(t, sKh + off);
                bh[2 * pq][0] = t[0]; bh[2 * pq][1] = t[1];
                bh[2 * pq + 1][0] = t[2]; bh[2 * pq + 1][1] = t[3];
            }
#pragma unroll
            for (int nj = 0; nj < 8; nj++)
                mma16816h(sacc[nj], qh[ks], bh[nj]);
        }

        // ---- online softmax ----
        float mloc[2] = {-1e30f, -1e30f};
#pragma unroll
        for (int nj = 0; nj < 8; nj++) {
            mloc[0] = fmaxf(mloc[0], fmaxf(sacc[nj][0], sacc[nj][1]));
            mloc[1] = fmaxf(mloc[1], fmaxf(sacc[nj][2], sacc[nj][3]));
        }
#pragma unroll
        for (int r = 0; r < 2; r++) {
            mloc[r] = fmaxf(mloc[r], __shfl_xor_sync(0xFFFFFFFFu, mloc[r], 1));
            mloc[r] = fmaxf(mloc[r], __shfl_xor_sync(0xFFFFFFFFu, mloc[r], 2));
        }
        float corr[2];
#pragma unroll
        for (int r = 0; r < 2; r++) {
            float mnew = fmaxf(mrun[r], mloc[r]);
            corr[r] = __expf(mrun[r] - mnew);
            mrun[r] = mnew;
        }
        float psum[2] = {0.f, 0.f};
#pragma unroll
        for (int nj = 0; nj < 8; nj++) {
            float p0 = __expf(sacc[nj][0] - mrun[0]);
            float p1 = __expf(sacc[nj][1] - mrun[0]);
            float p2 = __expf(sacc[nj][2] - mrun[1]);
            float p3 = __expf(sacc[nj][3] - mrun[1]);
            sacc[nj][0] = p0; sacc[nj][1] = p1;
            sacc[nj][2] = p2; sacc[nj][3] = p3;
            psum[0] += p0 + p1;
            psum[1] += p2 + p3;
        }
#pragma unroll
        for (int r = 0; r < 2; r++) {
            psum[r] += __shfl_xor_sync(0xFFFFFFFFu, psum[r], 1);
            psum[r] += __shfl_xor_sync(0xFFFFFFFFu, psum[r], 2);
            lrun[r] = lrun[r] * corr[r] + psum[r];
        }
#pragma unroll
        for (int dn = 0; dn < 8; dn++) {
            o[dn][0] *= corr[0]; o[dn][1] *= corr[0];
            o[dn][2] *= corr[1]; o[dn][3] *= corr[1];
        }

        // ---- repack P -> A-frags ----
        uint32_t ph[4][4];
#pragma unroll
        for (int ks = 0; ks < 4; ks++) {
            const float* c0 = sacc[2 * ks];
            const float* c1 = sacc[2 * ks + 1];
            ph[ks][0] = pack2h(c0[0], c0[1]);
            ph[ks][1] = pack2h(c0[2], c0[3]);
            ph[ks][2] = pack2h(c1[0], c1[1]);
            ph[ks][3] = pack2h(c1[2], c1[3]);
        }

        // ---- O += P V ----
#pragma unroll
        for (int ks = 0; ks < 4; ks++) {
            uint32_t vbh[8][2];
#pragma unroll
            for (int pq = 0; pq < 4; pq++) {
                uint32_t off = bufOff + (uint32_t)(((ks * 16 + v_row) * FLDV) + pq * 16 + v_col) * 2;
                uint32_t t[4];
                ldsm_x4_t(t, sVh + off);
                vbh[2 * pq][0] = t[0]; vbh[2 * pq][1] = t[1];
                vbh[2 * pq + 1][0] = t[2]; vbh[2 * pq + 1][1] = t[3];
            }
#pragma unroll
            for (int dn = 0; dn < 8; dn++)
                mma16816h(o[dn], ph[ks], vbh[dn]);
        }

        // ---- store prefetched tile into the other buffer ----
        if (hasNext) {
            const int eo = (p ^ 1) * (64 * FLDV) + lrow * FLDV + lcol;
            *(uint4*)(Kh + eo) = kh2[0]; *(uint4*)(Kh + eo + 8) = kh2[1];
            *(uint4*)(Vh + eo) = vh2[0]; *(uint4*)(Vh + eo + 8) = vh2[1];
        }
        __syncthreads();
        p ^= 1;
    }

    // ---- finalize: write ctx as fp16 [B,S,H] ----
    float inv0 = 1.0f / lrun[0];
    float inv1 = 1.0f / lrun[1];
#pragma unroll
    for (int dn = 0; dn < 8; dn++) {
        int d = h * HD_ + dn * 8 + t2;
        int m0g = q0 + warp * 16 + g;
        size_t off0 = ((size_t)b * S_ + m0g) * H_ + d;
        size_t off1 = ((size_t)b * S_ + m0g + 8) * H_ + d;
        *(uint32_t*)&Ch[off0] = pack2h(o[dn][0] * inv0, o[dn][1] * inv0);
        *(uint32_t*)&Ch[off1] = pack2h(o[dn][2] * inv1, o[dn][3] * inv1);
    }
}

// ---------------- layernorm (one block per row) --------------------------
__global__ __launch_bounds__(256) void layernorm_k(
    const float* __restrict__ hin, const float* __restrict__ gamma,
    const float* __restrict__ beta, float* __restrict__ out)
{
    const int row = blockIdx.x;
    const int t = threadIdx.x;
    const float* hp = hin + (size_t)row * H_;
    float* op = out + (size_t)row * H_;

    float4 x4 = ((const float4*)hp)[t];
    float sum = x4.x + x4.y + x4.z + x4.w;
    float sq  = x4.x * x4.x + x4.y * x4.y + x4.z * x4.z + x4.w * x4.w;

#pragma unroll
    for (int off = 16; off > 0; off >>= 1) {
        sum += __shfl_xor_sync(0xFFFFFFFFu, sum, off);
        sq  += __shfl_xor_sync(0xFFFFFFFFu, sq,  off);
    }
    __shared__ float ssum[8], ssq[8];
    const int wid = t >> 5, lid = t & 31;
    if (lid == 0) { ssum[wid] = sum; ssq[wid] = sq; }
    __syncthreads();
    if (wid == 0) {
        float a = (lid < 8) ? ssum[lid] : 0.f;
        float b = (lid < 8) ? ssq[lid]  : 0.f;
#pragma unroll
        for (int off = 4; off > 0; off >>= 1) {
            a += __shfl_xor_sync(0xFFFFFFFFu, a, off);
            b += __shfl_xor_sync(0xFFFFFFFFu, b, off);
        }
        if (lid == 0) { ssum[0] = a; ssq[0] = b; }
    }
    __syncthreads();
    const float mean = ssum[0] * (1.0f / H_);
    const float var  = ssq[0] * (1.0f / H_) - mean * mean;
    const float rstd = rsqrtf(var + 1e-12f);

    float4 g4 = ((const float4*)gamma)[t];
    float4 b4 = ((const float4*)beta)[t];
    float4 o4;
    o4.x = g4.x * (x4.x - mean) * rstd + b4.x;
    o4.y = g4.y * (x4.y - mean) * rstd + b4.y;
    o4.z = g4.z * (x4.z - mean) * rstd + b4.z;
    o4.w = g4.w * (x4.w - mean) * rstd + b4.w;
    ((float4*)op)[t] = o4;
}

// ---------------- launch ----------------
extern "C" void kernel_launch(void* const* d_in, const int* in_sizes, int n_in,
                              void* d_out, int out_size)
{
    const float* x     = (const float*)d_in[0];
    const float* wq    = (const float*)d_in[1];
    const float* bq    = (const float*)d_in[2];
    const float* wk    = (const float*)d_in[3];
    const float* bk    = (const float*)d_in[4];
    const float* wv    = (const float*)d_in[5];
    const float* bv    = (const float*)d_in[6];
    const float* wo    = (const float*)d_in[7];
    const float* bo    = (const float*)d_in[8];
    const float* gamma = (const float*)d_in[9];
    const float* beta  = (const float*)d_in[10];

    __half *xh, *wqh, *wkh, *wvh, *woh, *qh, *kh, *vh, *ch;
    float *hbuf;
    cudaGetSymbolAddress((void**)&xh,  g_xh);
    cudaGetSymbolAddress((void**)&wqh, g_wqh);
    cudaGetSymbolAddress((void**)&wkh, g_wkh);
    cudaGetSymbolAddress((void**)&wvh, g_wvh);
    cudaGetSymbolAddress((void**)&woh, g_woh);
    cudaGetSymbolAddress((void**)&qh,  g_qh);
    cudaGetSymbolAddress((void**)&kh,  g_kh);
    cudaGetSymbolAddress((void**)&vh,  g_vh);
    cudaGetSymbolAddress((void**)&ch,  g_ch);
    cudaGetSymbolAddress((void**)&hbuf, g_h);

    cudaFuncSetAttribute(gemm_pre,
                         cudaFuncAttributeMaxDynamicSharedMemorySize, GEMM_SMEM);
    cudaFuncSetAttribute(flash_mma,
                         cudaFuncAttributeMaxDynamicSharedMemorySize, FLASH_SMEM);

    // ---- prep: fp32 -> fp16 ----
    {
        const int XN4 = MTOT * H_ / 4;
        const int WN4 = H_ * H_ / 4;
        split_hi_only<<<(XN4 + 255) / 256, 256>>>((const float4*)x,  (uint2*)xh,  XN4);
        split_hi_only<<<(WN4 + 255) / 256, 256>>>((const float4*)wq, (uint2*)wqh, WN4);
        split_hi_only<<<(WN4 + 255) / 256, 256>>>((const float4*)wk, (uint2*)wkh, WN4);
        split_hi_only<<<(WN4 + 255) / 256, 256>>>((const float4*)wv, (uint2*)wvh, WN4);
        split_hi_only<<<(WN4 + 255) / 256, 256>>>((const float4*)wo, (uint2*)woh, WN4);
    }

    // ---- fused QKV projections (z selects weights; q scaled by 1/8) ----
    gemm_pre<<<dim3(H_ / BN, MTOT / BM, 3), 256, GEMM_SMEM>>>(
        xh, wqh, wkh, wvh, bq, bk, bv, qh, kh, vh, nullptr, nullptr, 1);

    // ---- flash attention ----
    flash_mma<<<dim3(S_ / 128, NH_, B_), 256, FLASH_SMEM>>>(qh, kh, vh, ch);

    // ---- output projection + residual (fp32 out) ----
    gemm_pre<<<dim3(H_ / BN, MTOT / BM, 1), 256, GEMM_SMEM>>>(
        ch, woh, woh, woh, bo, bo, bo, nullptr, nullptr, nullptr, hbuf, x, 0);

    layernorm_k<<<MTOT, 256>>>(hbuf, gamma, beta, (float*)d_out);
}

// round 16
// speedup vs baseline: 2.8243x; 1.0448x over previous
#include <cuda_runtime.h>
#include <cuda_fp16.h>
#include <math.h>
#include <stdint.h>

#define B_   4
#define S_   2048
#define H_   1024
#define NH_  16
#define HD_  64
#define MTOT (B_ * S_)   // 8192
#define HEADN ((size_t)B_ * NH_ * S_ * HD_)

// ---------------- scratch (no allocs allowed) ----------------
__device__ __half g_xh[(size_t)MTOT * H_];
__device__ __half g_wqh[(size_t)H_ * H_];
__device__ __half g_wkh[(size_t)H_ * H_];
__device__ __half g_wvh[(size_t)H_ * H_];
__device__ __half g_woh[(size_t)H_ * H_];
__device__ __half g_qh[HEADN];
__device__ __half g_kh[HEADN];
__device__ __half g_vh[HEADN];
__device__ __half g_ch[(size_t)MTOT * H_];
__device__ float g_h[(size_t)MTOT * H_];      // pre-LN fp32

// ---------------- common PTX helpers ----------------
__device__ __forceinline__ void mma16816h(float* c, const uint32_t* a, const uint32_t* b) {
    asm volatile(
        "mma.sync.aligned.m16n8k16.row.col.f32.f16.f16.f32 "
        "{%0,%1,%2,%3}, {%4,%5,%6,%7}, {%8,%9}, {%0,%1,%2,%3};\n"
        : "+f"(c[0]), "+f"(c[1]), "+f"(c[2]), "+f"(c[3])
        : "r"(a[0]), "r"(a[1]), "r"(a[2]), "r"(a[3]), "r"(b[0]), "r"(b[1]));
}
__device__ __forceinline__ void ldsm_x4(uint32_t* r, uint32_t addr) {
    asm volatile(
        "ldmatrix.sync.aligned.m8n8.x4.shared.b16 {%0,%1,%2,%3}, [%4];\n"
        : "=r"(r[0]), "=r"(r[1]), "=r"(r[2]), "=r"(r[3]) : "r"(addr));
}
__device__ __forceinline__ void ldsm_x4_t(uint32_t* r, uint32_t addr) {
    asm volatile(
        "ldmatrix.sync.aligned.m8n8.x4.trans.shared.b16 {%0,%1,%2,%3}, [%4];\n"
        : "=r"(r[0]), "=r"(r[1]), "=r"(r[2]), "=r"(r[3]) : "r"(addr));
}
__device__ __forceinline__ uint32_t pack2h(float x, float y) {
    __half2 h2 = __floats2half2_rn(x, y);
    return *(uint32_t*)&h2;
}

// ---------------- prep: fp32 -> fp16 ----------------
__global__ __launch_bounds__(256) void split_x(
    const float4* __restrict__ src, uint2* __restrict__ dh, int n4)
{
    int i = blockIdx.x * blockDim.x + threadIdx.x;
    if (i >= n4) return;
    float4 f = src[i];
    dh[i] = make_uint2(pack2h(f.x, f.y), pack2h(f.z, f.w));
}
// all 4 weight matrices in one launch; blockIdx.y selects the matrix
__global__ __launch_bounds__(256) void split_w4(
    const float4* __restrict__ w0, const float4* __restrict__ w1,
    const float4* __restrict__ w2, const float4* __restrict__ w3,
    uint2* __restrict__ d0, uint2* __restrict__ d1,
    uint2* __restrict__ d2, uint2* __restrict__ d3, int n4)
{
    int i = blockIdx.x * blockDim.x + threadIdx.x;
    if (i >= n4) return;
    const int m = blockIdx.y;
    const float4* src = (m == 0) ? w0 : (m == 1) ? w1 : (m == 2) ? w2 : w3;
    uint2* dst = (m == 0) ? d0 : (m == 1) ? d1 : (m == 2) ? d2 : d3;
    float4 f = src[i];
    dst[i] = make_uint2(pack2h(f.x, f.y), pack2h(f.z, f.w));
}

// ============================================================
//  fp16 tensor-core GEMM: C = A * W^T + bias
//  CTA 128x128, BK=32, double-buffered dynamic smem, 2 CTA/SM.
// ============================================================
#define BM 128
#define BN 128
#define BK 32
#define LDS_PAD 8
#define LDK (BK + LDS_PAD)      // 40 halves = 80 B row stride
#define G_ARR (2 * BM * LDK * 2)          // 20480 B per array (2 buffers)
#define GEMM_SMEM (2 * G_ARR)             // 40960 B  (A, B)

// folded Q scale: (1/8) * log2(e)  — softmax done in base-2
#define QSCALE 0.1803368801111204f

__global__ __launch_bounds__(256, 2) void gemm_pre(
    const __half* __restrict__ Ah_,
    const __half* __restrict__ Wh0, const __half* __restrict__ Wh1, const __half* __restrict__ Wh2,
    const float* __restrict__ bias0, const float* __restrict__ bias1, const float* __restrict__ bias2,
    __half* __restrict__ Oq, __half* __restrict__ Ok, __half* __restrict__ Ov,
    float* __restrict__ Cf, const float* __restrict__ resid, int qkv_layout)
{
    extern __shared__ char smem[];
    const int K = H_;
    const int z = blockIdx.z;
    const __half* Wh = (z == 0) ? Wh0 : (z == 1) ? Wh1 : Wh2;
    const float* bias = (z == 0) ? bias0 : (z == 1) ? bias1 : bias2;
    __half* Oc = (z == 0) ? Oq : (z == 1) ? Ok : Ov;
    const float scale = (qkv_layout && z == 0) ? QSCALE : 1.0f;

    __half* sA = (__half*)(smem);
    __half* sB = (__half*)(smem + G_ARR);

    const int tid  = threadIdx.x;
    const int warp = tid >> 5;
    const int lane = tid & 31;
    const int rowBase = blockIdx.y * BM;
    const int colBase = blockIdx.x * BN;

    const int m0 = (warp >> 1) * 32;
    const int n0 = (warp & 1) * 64;

    const int lrow = tid >> 1;
    const int lcol = (tid & 1) * 16;
    const __half* Ag = Ah_ + (size_t)(rowBase + lrow) * K + lcol;
    const __half* Wg = Wh + (size_t)(colBase + lrow) * K + lcol;

    const int a_row = m0 + ((lane >> 3) & 1) * 8 + (lane & 7);
    const int a_col = ((lane >> 4) & 1) * 8;
    const int b_row = n0 + ((lane >> 4) & 1) * 8 + (lane & 7);
    const int b_col = ((lane >> 3) & 1) * 8;

    const uint32_t bufStride = (uint32_t)(BM * LDK * 2);
    const uint32_t sAU = (uint32_t)__cvta_generic_to_shared(sA);
    const uint32_t sBU = (uint32_t)__cvta_generic_to_shared(sB);

    float acc[2][8][4];
#pragma unroll
    for (int i = 0; i < 2; i++)
#pragma unroll
        for (int j = 0; j < 8; j++)
#pragma unroll
            for (int r = 0; r < 4; r++) acc[i][j][r] = 0.f;

    uint4 ra[2], rb[2];
    ra[0] = *(const uint4*)(Ag);     ra[1] = *(const uint4*)(Ag + 8);
    rb[0] = *(const uint4*)(Wg);     rb[1] = *(const uint4*)(Wg + 8);
    {
        const int eo = lrow * LDK + lcol;
        *(uint4*)(sA + eo) = ra[0]; *(uint4*)(sA + eo + 8) = ra[1];
        *(uint4*)(sB + eo) = rb[0]; *(uint4*)(sB + eo + 8) = rb[1];
    }
    __syncthreads();

    int p = 0;
    for (int kt = 0; kt < K; kt += BK) {
        const bool hasNext = (kt + BK < K);
        if (hasNext) {
            ra[0] = *(const uint4*)(Ag + kt + BK);  ra[1] = *(const uint4*)(Ag + kt + BK + 8);
            rb[0] = *(const uint4*)(Wg + kt + BK);  rb[1] = *(const uint4*)(Wg + kt + BK + 8);
        }

        const uint32_t bufOff = (uint32_t)p * bufStride;
#pragma unroll
        for (int ks = 0; ks < 2; ks++) {
            const int kb = ks * 16;
            uint32_t ah[2][4], bh[8][2];
#pragma unroll
            for (int mi = 0; mi < 2; mi++) {
                uint32_t off = bufOff + (uint32_t)(((a_row + mi * 16) * LDK) + kb + a_col) * 2;
                ldsm_x4(ah[mi], sAU + off);
            }
#pragma unroll
            for (int pq = 0; pq < 4; pq++) {
                uint32_t off = bufOff + (uint32_t)(((b_row + pq * 16) * LDK) + kb + b_col) * 2;
                uint32_t t[4];
                ldsm_x4(t, sBU + off);
                bh[2 * pq][0] = t[0]; bh[2 * pq][1] = t[1];
                bh[2 * pq + 1][0] = t[2]; bh[2 * pq + 1][1] = t[3];
            }
#pragma unroll
            for (int nj = 0; nj < 8; nj++)
#pragma unroll
                for (int mi = 0; mi < 2; mi++)
                    mma16816h(acc[mi][nj], ah[mi], bh[nj]);
        }

        if (hasNext) {
            const int eo = (p ^ 1) * (BM * LDK) + lrow * LDK + lcol;
            *(uint4*)(sA + eo) = ra[0]; *(uint4*)(sA + eo + 8) = ra[1];
            *(uint4*)(sB + eo) = rb[0]; *(uint4*)(sB + eo + 8) = rb[1];
        }
        __syncthreads();
        p ^= 1;
    }

    const int g  = lane >> 2;
    const int t2 = (lane & 3) * 2;
#pragma unroll
    for (int mi = 0; mi < 2; mi++) {
#pragma unroll
        for (int nj = 0; nj < 8; nj++) {
            int n = colBase + n0 + nj * 8 + t2;
            float bia0 = bias[n], bia1 = bias[n + 1];
#pragma unroll
            for (int rr = 0; rr < 2; rr++) {
                int m = rowBase + m0 + mi * 16 + g + rr * 8;
                float v0 = acc[mi][nj][rr * 2 + 0] + bia0;
                float v1 = acc[mi][nj][rr * 2 + 1] + bia1;
                if (qkv_layout) {
                    int bb = m >> 11, ss = m & (S_ - 1);
                    int hh = n >> 6, dd = n & (HD_ - 1);
                    size_t off = ((((size_t)bb * NH_) + hh) * S_ + ss) * HD_ + dd;
                    *(uint32_t*)&Oc[off] = pack2h(v0 * scale, v1 * scale);
                } else {
                    const float2 rs = *(const float2*)&resid[(size_t)m * H_ + n];
                    *(float2*)&Cf[(size_t)m * H_ + n] = make_float2(v0 + rs.x, v1 + rs.y);
                }
            }
        }
    }
}

// ============================================================
//  fp16 flash attention, 128 q x 64 kv tiles, 256 threads,
//  base-2 softmax (scale folded into Q), 2 CTA/SM.
// ============================================================
#define FLDV 72
#define F_ARR (2 * 64 * FLDV * 2)          // 18432 B (both buffers)
#define FLASH_SMEM (2 * F_ARR)             // 36864 B (K, V)

__global__ __launch_bounds__(256, 2) void flash_mma(
    const __half* __restrict__ Qh, const __half* __restrict__ Kgh,
    const __half* __restrict__ Vgh, __half* __restrict__ Ch)
{
    extern __shared__ char smem[];
    __half* Kh = (__half*)(smem);
    __half* Vh = (__half*)(smem + F_ARR);

    const int b = blockIdx.z;
    const int h = blockIdx.y;
    const int tid  = threadIdx.x;
    const int warp = tid >> 5;
    const int lane = tid & 31;
    const int q0 = blockIdx.x * 128;

    const size_t headBase = (((size_t)b * NH_ + h) * S_) * HD_;

    const int lrow = tid >> 2;
    const int lcol = (tid & 3) * 16;

    const int b_row = ((lane >> 4) & 1) * 8 + (lane & 7);
    const int b_col = ((lane >> 3) & 1) * 8;
    const int v_row = ((lane >> 3) & 1) * 8 + (lane & 7);
    const int v_col = ((lane >> 4) & 1) * 8;

    const uint32_t bufStride = (uint32_t)(64 * FLDV * 2);
    const uint32_t sKh = (uint32_t)__cvta_generic_to_shared(Kh);
    const uint32_t sVh = (uint32_t)__cvta_generic_to_shared(Vh);

    const int g  = lane >> 2;
    const int t2 = (lane & 3) * 2;

    // ---- Q fragments straight from gmem (scale*log2e folded) ----
    uint32_t qh[4][4];
    {
        const __half* qh0 = Qh + headBase + (size_t)(q0 + warp * 16 + g) * HD_;
        const __half* qh1 = qh0 + 8 * HD_;
#pragma unroll
        for (int ks = 0; ks < 4; ks++) {
            int c = ks * 16 + t2;
            qh[ks][0] = *(const uint32_t*)(qh0 + c);
            qh[ks][1] = *(const uint32_t*)(qh1 + c);
            qh[ks][2] = *(const uint32_t*)(qh0 + c + 8);
            qh[ks][3] = *(const uint32_t*)(qh1 + c + 8);
        }
    }

    float o[8][4];
#pragma unroll
    for (int dn = 0; dn < 8; dn++)
#pragma unroll
        for (int e = 0; e < 4; e++) o[dn][e] = 0.f;
    float mrun[2] = {-1e30f, -1e30f};
    float lrun[2] = {0.f, 0.f};

    // ---- prologue: tile 0 -> regs -> buffer 0 ----
    uint4 kh2[2], vh2[2];
    {
        const __half* kg = Kgh + headBase + (size_t)lrow * HD_ + lcol;
        const __half* vg = Vgh + headBase + (size_t)lrow * HD_ + lcol;
        kh2[0] = *(const uint4*)(kg); kh2[1] = *(const uint4*)(kg + 8);
        vh2[0] = *(const uint4*)(vg); vh2[1] = *(const uint4*)(vg + 8);
        const int eo = lrow * FLDV + lcol;
        *(uint4*)(Kh + eo) = kh2[0]; *(uint4*)(Kh + eo + 8) = kh2[1];
        *(uint4*)(Vh + eo) = vh2[0]; *(uint4*)(Vh + eo + 8) = vh2[1];
    }
    __syncthreads();

    int p = 0;
    for (int j0 = 0; j0 < S_; j0 += 64) {
        const bool hasNext = (j0 + 64 < S_);
        if (hasNext) {
            const __half* kg = Kgh + headBase + (size_t)(j0 + 64 + lrow) * HD_ + lcol;
            const __half* vg = Vgh + headBase + (size_t)(j0 + 64 + lrow) * HD_ + lcol;
            kh2[0] = *(const uint4*)(kg); kh2[1] = *(const uint4*)(kg + 8);
            vh2[0] = *(const uint4*)(vg); vh2[1] = *(const uint4*)(vg + 8);
        }

        const uint32_t bufOff = (uint32_t)p * bufStride;

        // ---- S = Q K^T  (already in log2 domain) ----
        float sacc[8][4];
#pragma unroll
        for (int nj = 0; nj < 8; nj++)
#pragma unroll
            for (int e = 0; e < 4; e++) sacc[nj][e] = 0.f;

#pragma unroll
        for (int ks = 0; ks < 4; ks++) {
            uint32_t bh[8][2];
#pragma unroll
            for (int pq = 0; pq < 4; pq++) {
                uint32_t off = bufOff + (uint32_t)(((pq * 16 + b_row) * FLDV) + ks * 16 + b_col) * 2;
                uint32_t t[4];
                ldsm_x4(t, sKh + off);
                bh[2 * pq][0] = t[0]; bh[2 * pq][1] = t[1];
                bh[2 * pq + 1][0] = t[2]; bh[2 * pq + 1][1] = t[3];
            }
#pragma unroll
            for (int nj = 0; nj < 8; nj++)
                mma16816h(sacc[nj], qh[ks], bh[nj]);
        }

        // ---- online softmax (base-2) ----
        float mloc[2] = {-1e30f, -1e30f};
#pragma unroll
        for (int nj = 0; nj < 8; nj++) {
            mloc[0] = fmaxf(mloc[0], fmaxf(sacc[nj][0], sacc[nj][1]));
            mloc[1] = fmaxf(mloc[1], fmaxf(sacc[nj][2], sacc[nj][3]));
        }
#pragma unroll
        for (int r = 0; r < 2; r++) {
            mloc[r] = fmaxf(mloc[r], __shfl_xor_sync(0xFFFFFFFFu, mloc[r], 1));
            mloc[r] = fmaxf(mloc[r], __shfl_xor_sync(0xFFFFFFFFu, mloc[r], 2));
        }
        float corr[2];
#pragma unroll
        for (int r = 0; r < 2; r++) {
            float mnew = fmaxf(mrun[r], mloc[r]);
            corr[r] = exp2f(mrun[r] - mnew);
            mrun[r] = mnew;
        }
        float psum[2] = {0.f, 0.f};
#pragma unroll
        for (int nj = 0; nj < 8; nj++) {
            float p0 = exp2f(sacc[nj][0] - mrun[0]);
            float p1 = exp2f(sacc[nj][1] - mrun[0]);
            float p2 = exp2f(sacc[nj][2] - mrun[1]);
            float p3 = exp2f(sacc[nj][3] - mrun[1]);
            sacc[nj][0] = p0; sacc[nj][1] = p1;
            sacc[nj][2] = p2; sacc[nj][3] = p3;
            psum[0] += p0 + p1;
            psum[1] += p2 + p3;
        }
#pragma unroll
        for (int r = 0; r < 2; r++) {
            psum[r] += __shfl_xor_sync(0xFFFFFFFFu, psum[r], 1);
            psum[r] += __shfl_xor_sync(0xFFFFFFFFu, psum[r], 2);
            lrun[r] = lrun[r] * corr[r] + psum[r];
        }
#pragma unroll
        for (int dn = 0; dn < 8; dn++) {
            o[dn][0] *= corr[0]; o[dn][1] *= corr[0];
            o[dn][2] *= corr[1]; o[dn][3] *= corr[1];
        }

        // ---- repack P -> A-frags ----
        uint32_t ph[4][4];
#pragma unroll
        for (int ks = 0; ks < 4; ks++) {
            const float* c0 = sacc[2 * ks];
            const float* c1 = sacc[2 * ks + 1];
            ph[ks][0] = pack2h(c0[0], c0[1]);
            ph[ks][1] = pack2h(c0[2], c0[3]);
            ph[ks][2] = pack2h(c1[0], c1[1]);
            ph[ks][3] = pack2h(c1[2], c1[3]);
        }

        // ---- O += P V ----
#pragma unroll
        for (int ks = 0; ks < 4; ks++) {
            uint32_t vbh[8][2];
#pragma unroll
            for (int pq = 0; pq < 4; pq++) {
                uint32_t off = bufOff + (uint32_t)(((ks * 16 + v_row) * FLDV) + pq * 16 + v_col) * 2;
                uint32_t t[4];
                ldsm_x4_t(t, sVh + off);
                vbh[2 * pq][0] = t[0]; vbh[2 * pq][1] = t[1];
                vbh[2 * pq + 1][0] = t[2]; vbh[2 * pq + 1][1] = t[3];
            }
#pragma unroll
            for (int dn = 0; dn < 8; dn++)
                mma16816h(o[dn], ph[ks], vbh[dn]);
        }

        // ---- store prefetched tile into the other buffer ----
        if (hasNext) {
            const int eo = (p ^ 1) * (64 * FLDV) + lrow * FLDV + lcol;
            *(uint4*)(Kh + eo) = kh2[0]; *(uint4*)(Kh + eo + 8) = kh2[1];
            *(uint4*)(Vh + eo) = vh2[0]; *(uint4*)(Vh + eo + 8) = vh2[1];
        }
        __syncthreads();
        p ^= 1;
    }

    // ---- finalize: write ctx as fp16 [B,S,H] ----
    float inv0 = 1.0f / lrun[0];
    float inv1 = 1.0f / lrun[1];
#pragma unroll
    for (int dn = 0; dn < 8; dn++) {
        int d = h * HD_ + dn * 8 + t2;
        int m0g = q0 + warp * 16 + g;
        size_t off0 = ((size_t)b * S_ + m0g) * H_ + d;
        size_t off1 = ((size_t)b * S_ + m0g + 8) * H_ + d;
        *(uint32_t*)&Ch[off0] = pack2h(o[dn][0] * inv0, o[dn][1] * inv0);
        *(uint32_t*)&Ch[off1] = pack2h(o[dn][2] * inv1, o[dn][3] * inv1);
    }
}

// ---------------- layernorm (one block per row) --------------------------
__global__ __launch_bounds__(256) void layernorm_k(
    const float* __restrict__ hin, const float* __restrict__ gamma,
    const float* __restrict__ beta, float* __restrict__ out)
{
    const int row = blockIdx.x;
    const int t = threadIdx.x;
    const float* hp = hin + (size_t)row * H_;
    float* op = out + (size_t)row * H_;

    float4 x4 = ((const float4*)hp)[t];
    float sum = x4.x + x4.y + x4.z + x4.w;
    float sq  = x4.x * x4.x + x4.y * x4.y + x4.z * x4.z + x4.w * x4.w;

#pragma unroll
    for (int off = 16; off > 0; off >>= 1) {
        sum += __shfl_xor_sync(0xFFFFFFFFu, sum, off);
        sq  += __shfl_xor_sync(0xFFFFFFFFu, sq,  off);
    }
    __shared__ float ssum[8], ssq[8];
    const int wid = t >> 5, lid = t & 31;
    if (lid == 0) { ssum[wid] = sum; ssq[wid] = sq; }
    __syncthreads();
    if (wid == 0) {
        float a = (lid < 8) ? ssum[lid] : 0.f;
        float b = (lid < 8) ? ssq[lid]  : 0.f;
#pragma unroll
        for (int off = 4; off > 0; off >>= 1) {
            a += __shfl_xor_sync(0xFFFFFFFFu, a, off);
            b += __shfl_xor_sync(0xFFFFFFFFu, b, off);
        }
        if (lid == 0) { ssum[0] = a; ssq[0] = b; }
    }
    __syncthreads();
    const float mean = ssum[0] * (1.0f / H_);
    const float var  = ssq[0] * (1.0f / H_) - mean * mean;
    const float rstd = rsqrtf(var + 1e-12f);

    float4 g4 = ((const float4*)gamma)[t];
    float4 b4 = ((const float4*)beta)[t];
    float4 o4;
    o4.x = g4.x * (x4.x - mean) * rstd + b4.x;
    o4.y = g4.y * (x4.y - mean) * rstd + b4.y;
    o4.z = g4.z * (x4.z - mean) * rstd + b4.z;
    o4.w = g4.w * (x4.w - mean) * rstd + b4.w;
    ((float4*)op)[t] = o4;
}

// ---------------- launch ----------------
extern "C" void kernel_launch(void* const* d_in, const int* in_sizes, int n_in,
                              void* d_out, int out_size)
{
    const float* x     = (const float*)d_in[0];
    const float* wq    = (const float*)d_in[1];
    const float* bq    = (const float*)d_in[2];
    const float* wk    = (const float*)d_in[3];
    const float* bk    = (const float*)d_in[4];
    const float* wv    = (const float*)d_in[5];
    const float* bv    = (const float*)d_in[6];
    const float* wo    = (const float*)d_in[7];
    const float* bo    = (const float*)d_in[8];
    const float* gamma = (const float*)d_in[9];
    const float* beta  = (const float*)d_in[10];

    __half *xh, *wqh, *wkh, *wvh, *woh, *qh, *kh, *vh, *ch;
    float *hbuf;
    cudaGetSymbolAddress((void**)&xh,  g_xh);
    cudaGetSymbolAddress((void**)&wqh, g_wqh);
    cudaGetSymbolAddress((void**)&wkh, g_wkh);
    cudaGetSymbolAddress((void**)&wvh, g_wvh);
    cudaGetSymbolAddress((void**)&woh, g_woh);
    cudaGetSymbolAddress((void**)&qh,  g_qh);
    cudaGetSymbolAddress((void**)&kh,  g_kh);
    cudaGetSymbolAddress((void**)&vh,  g_vh);
    cudaGetSymbolAddress((void**)&ch,  g_ch);
    cudaGetSymbolAddress((void**)&hbuf, g_h);

    cudaFuncSetAttribute(gemm_pre,
                         cudaFuncAttributeMaxDynamicSharedMemorySize, GEMM_SMEM);
    cudaFuncSetAttribute(flash_mma,
                         cudaFuncAttributeMaxDynamicSharedMemorySize, FLASH_SMEM);

    // ---- prep: fp32 -> fp16 (2 launches) ----
    {
        const int XN4 = MTOT * H_ / 4;
        const int WN4 = H_ * H_ / 4;
        split_x<<<(XN4 + 255) / 256, 256>>>((const float4*)x, (uint2*)xh, XN4);
        split_w4<<<dim3((WN4 + 255) / 256, 4), 256>>>(
            (const float4*)wq, (const float4*)wk, (const float4*)wv, (const float4*)wo,
            (uint2*)wqh, (uint2*)wkh, (uint2*)wvh, (uint2*)woh, WN4);
    }

    // ---- fused QKV projections (z selects weights; q scaled by 1/8*log2e) ----
    gemm_pre<<<dim3(H_ / BN, MTOT / BM, 3), 256, GEMM_SMEM>>>(
        xh, wqh, wkh, wvh, bq, bk, bv, qh, kh, vh, nullptr, nullptr, 1);

    // ---- flash attention (base-2 softmax) ----
    flash_mma<<<dim3(S_ / 128, NH_, B_), 256, FLASH_SMEM>>>(qh, kh, vh, ch);

    // ---- output projection + residual (fp32 out) ----
    gemm_pre<<<dim3(H_ / BN, MTOT / BM, 1), 256, GEMM_SMEM>>>(
        ch, woh, woh, woh, bo, bo, bo, nullptr, nullptr, nullptr, hbuf, x, 0);

    layernorm_k<<<MTOT, 256>>>(hbuf, gamma, beta, (float*)d_out);
}